// round 1
// baseline (speedup 1.0000x reference)
#include <cuda_runtime.h>
#include <math.h>

// Problem constants
#define F      65536      // frames
#define K1     512        // input len
#define MEM    128        // memory channels
#define NC     128        // scan chunks
#define CHUNK  512        // frames per chunk
#define TSCAN  65535      // scan length (frames 0..65534)

// Scratch (no cudaMalloc allowed)
__device__ float g_a[(size_t)F * MEM];     // a[t][c] = left*right
__device__ float g_b[(size_t)F * MEM];     // b[t][c] = 1-left
__device__ float g_z[(size_t)F * MEM];     // z[t][c]
__device__ float g_SA[NC * MEM];
__device__ float g_SB[NC * MEM];
__device__ float g_Cin[NC * MEM];

__device__ __forceinline__ float sigmoidf_(float x) {
    return 1.0f / (1.0f + __expf(-x));
}

// ---------------------------------------------------------------------------
// Kernel 1: h = sigmoid(W1 @ X + B1); a = h_l*h_r; b = 1-h_l  (frame-major out)
// Tile: all 256 rows x 64 frames, BK=64. 256 threads, 8x8 micro-tile where the
// 8 rows are {mi*4..+3} U {128+mi*4..+3}  -> left/right pairs live in-thread.
// ---------------------------------------------------------------------------
#define BN1 64
#define BK1 64
#define SMEM1 ((BK1 * 256 + BK1 * BN1) * 4)   // 80 KB

__global__ __launch_bounds__(256) void k1_gemm1(
    const float* __restrict__ X,
    const float* __restrict__ W1,
    const float* __restrict__ B1)
{
    extern __shared__ float sm[];
    float* Wsm = sm;                 // [BK1][256]  (k-major, transposed)
    float* Xsm = sm + BK1 * 256;     // [BK1][BN1]

    const int tid = threadIdx.x;
    const int mi  = tid & 31;        // row group 0..31
    const int ni  = tid >> 5;        // frame group 0..7
    const int t0  = blockIdx.x * BN1;

    float acc[8][8];
    #pragma unroll
    for (int r = 0; r < 8; r++)
        #pragma unroll
        for (int n = 0; n < 8; n++) acc[r][n] = 0.0f;

    for (int kb = 0; kb < K1; kb += BK1) {
        // W tile: thread 'tid' loads its own W1 row -> conflict-free STS
        const float4* wp = (const float4*)(W1 + (size_t)tid * K1 + kb);
        #pragma unroll
        for (int i = 0; i < 16; i++) {
            float4 v = wp[i];
            Wsm[(i * 4 + 0) * 256 + tid] = v.x;
            Wsm[(i * 4 + 1) * 256 + tid] = v.y;
            Wsm[(i * 4 + 2) * 256 + tid] = v.z;
            Wsm[(i * 4 + 3) * 256 + tid] = v.w;
        }
        // X tile: coalesced float4 loads
        #pragma unroll
        for (int i = 0; i < 4; i++) {
            int f  = tid + (i << 8);
            int k  = f >> 4;
            int c4 = (f & 15) << 2;
            float4 v = *(const float4*)(X + (size_t)(kb + k) * F + t0 + c4);
            *(float4*)&Xsm[k * BN1 + c4] = v;
        }
        __syncthreads();

        #pragma unroll 8
        for (int k = 0; k < BK1; k++) {
            float4 wl = *(float4*)&Wsm[k * 256 + mi * 4];
            float4 wr = *(float4*)&Wsm[k * 256 + 128 + mi * 4];
            float4 x0 = *(float4*)&Xsm[k * BN1 + ni * 8];
            float4 x1 = *(float4*)&Xsm[k * BN1 + ni * 8 + 4];
            float wv[8] = {wl.x, wl.y, wl.z, wl.w, wr.x, wr.y, wr.z, wr.w};
            float xv[8] = {x0.x, x0.y, x0.z, x0.w, x1.x, x1.y, x1.z, x1.w};
            #pragma unroll
            for (int r = 0; r < 8; r++)
                #pragma unroll
                for (int n = 0; n < 8; n++)
                    acc[r][n] = fmaf(wv[r], xv[n], acc[r][n]);
        }
        __syncthreads();
    }

    // Epilogue: sigmoid + a/b, written frame-major (coalesced 512B rows)
    float bl[4], br[4];
    #pragma unroll
    for (int j = 0; j < 4; j++) {
        bl[j] = B1[mi * 4 + j];
        br[j] = B1[128 + mi * 4 + j];
    }
    #pragma unroll
    for (int n = 0; n < 8; n++) {
        int t = t0 + ni * 8 + n;
        float4 av, bv;
        float* ap = (float*)&av;
        float* bp = (float*)&bv;
        #pragma unroll
        for (int j = 0; j < 4; j++) {
            float hl = sigmoidf_(acc[j][n] + bl[j]);
            float hr = sigmoidf_(acc[4 + j][n] + br[j]);
            ap[j] = hl * hr;
            bp[j] = 1.0f - hl;
        }
        *(float4*)&g_a[(size_t)t * MEM + mi * 4] = av;
        *(float4*)&g_b[(size_t)t * MEM + mi * 4] = bv;
    }
}

// ---------------------------------------------------------------------------
// Kernel 2: per-chunk scan reduce. Thread c walks its channel sequentially.
// Per step the block reads one contiguous 512B row of a and of b.
// ---------------------------------------------------------------------------
__global__ __launch_bounds__(128) void k2_reduce()
{
    const int c = threadIdx.x;
    const int j = blockIdx.x;
    const int tb = j * CHUNK;
    const int te = min(tb + CHUNK, TSCAN);
    float A = 1.0f, B = 0.0f;
    #pragma unroll 4
    for (int t = tb; t < te; t++) {
        float a = g_a[(size_t)t * MEM + c];
        float b = g_b[(size_t)t * MEM + c];
        B = fmaf(a, B, b);
        A *= a;
    }
    g_SA[j * MEM + c] = A;
    g_SB[j * MEM + c] = B;
}

// ---------------------------------------------------------------------------
// Kernel 3: sequential exclusive scan over the 128 chunk summaries.
// ---------------------------------------------------------------------------
__global__ __launch_bounds__(128) void k3_carry()
{
    const int c = threadIdx.x;
    float B = 0.0f;
    for (int j = 0; j < NC; j++) {
        g_Cin[j * MEM + c] = B;
        B = fmaf(g_SA[j * MEM + c], B, g_SB[j * MEM + c]);
    }
}

// ---------------------------------------------------------------------------
// Kernel 4: apply carry, write z frame-major. z[0][:]=0, z[t+1][:]=bb_t.
// ---------------------------------------------------------------------------
__global__ __launch_bounds__(128) void k4_apply()
{
    const int c = threadIdx.x;
    const int j = blockIdx.x;
    const int tb = j * CHUNK;
    const int te = min(tb + CHUNK, TSCAN);
    float B = g_Cin[j * MEM + c];
    if (j == 0) g_z[c] = 0.0f;
    #pragma unroll 4
    for (int t = tb; t < te; t++) {
        float a = g_a[(size_t)t * MEM + c];
        float b = g_b[(size_t)t * MEM + c];
        B = fmaf(a, B, b);
        g_z[(size_t)(t + 1) * MEM + c] = B;
    }
}

// ---------------------------------------------------------------------------
// Kernel 5: out = 1 - sigmoid(W2 @ z + B2) = 1/(1+exp(v)).
// W2 fully resident in SMEM (transposed [k][m]); z tile kept frame-major and
// read as warp-uniform broadcasts (warp lanes share ni -> same address).
// ---------------------------------------------------------------------------
#define BN2 64
#define SMEM2 ((128 * 256 + BN2 * 128) * 4)   // 160 KB

__global__ __launch_bounds__(256) void k5_gemm2(
    const float* __restrict__ W2,
    const float* __restrict__ B2,
    float* __restrict__ out)
{
    extern __shared__ float sm[];
    float* Wsm = sm;               // [128][256] transposed
    float* Zsm = sm + 128 * 256;   // [BN2][128] frame-major

    const int tid = threadIdx.x;
    const int mi  = tid & 31;
    const int ni  = tid >> 5;
    const int t0  = blockIdx.x * BN2;

    // W2: thread 'tid' loads its own row (conflict-free STS)
    const float4* wp = (const float4*)(W2 + (size_t)tid * MEM);
    #pragma unroll
    for (int i = 0; i < 32; i++) {
        float4 v = wp[i];
        Wsm[(i * 4 + 0) * 256 + tid] = v.x;
        Wsm[(i * 4 + 1) * 256 + tid] = v.y;
        Wsm[(i * 4 + 2) * 256 + tid] = v.z;
        Wsm[(i * 4 + 3) * 256 + tid] = v.w;
    }
    // z tile: coalesced
    #pragma unroll
    for (int i = 0; i < 8; i++) {
        int f  = tid + (i << 8);
        int n  = f >> 5;
        int c4 = (f & 31) << 2;
        float4 v = *(const float4*)(g_z + (size_t)(t0 + n) * MEM + c4);
        *(float4*)&Zsm[n * MEM + c4] = v;
    }
    __syncthreads();

    float acc[8][8];
    #pragma unroll
    for (int r = 0; r < 8; r++)
        #pragma unroll
        for (int n = 0; n < 8; n++) acc[r][n] = 0.0f;

    #pragma unroll 8
    for (int k = 0; k < MEM; k++) {
        float4 wl = *(float4*)&Wsm[k * 256 + mi * 4];
        float4 wr = *(float4*)&Wsm[k * 256 + 128 + mi * 4];
        float wv[8] = {wl.x, wl.y, wl.z, wl.w, wr.x, wr.y, wr.z, wr.w};
        #pragma unroll
        for (int n = 0; n < 8; n++) {
            float zv = Zsm[(ni * 8 + n) * MEM + k];   // warp-uniform broadcast
            #pragma unroll
            for (int r = 0; r < 8; r++)
                acc[r][n] = fmaf(wv[r], zv, acc[r][n]);
        }
    }

    // Epilogue: out = 1/(1+exp(acc + B2))
    #pragma unroll
    for (int rr = 0; rr < 8; rr++) {
        int r = (rr < 4) ? (mi * 4 + rr) : (128 + mi * 4 + (rr - 4));
        float b2 = B2[r];
        float4 o0, o1;
        float* o0p = (float*)&o0;
        float* o1p = (float*)&o1;
        #pragma unroll
        for (int n = 0; n < 4; n++)
            o0p[n] = 1.0f / (1.0f + __expf(acc[rr][n] + b2));
        #pragma unroll
        for (int n = 4; n < 8; n++)
            o1p[n - 4] = 1.0f / (1.0f + __expf(acc[rr][n] + b2));
        *(float4*)&out[(size_t)r * F + t0 + ni * 8]     = o0;
        *(float4*)&out[(size_t)r * F + t0 + ni * 8 + 4] = o1;
    }
}

// ---------------------------------------------------------------------------
extern "C" void kernel_launch(void* const* d_in, const int* in_sizes, int n_in,
                              void* d_out, int out_size)
{
    const float* X  = (const float*)d_in[0];  // (512, 65536)
    const float* W1 = (const float*)d_in[1];  // (256, 512)
    const float* B1 = (const float*)d_in[2];  // (256, 1)
    const float* W2 = (const float*)d_in[3];  // (256, 128)
    const float* B2 = (const float*)d_in[4];  // (256, 1)
    float* out = (float*)d_out;               // (256, 65536)

    cudaFuncSetAttribute(k1_gemm1, cudaFuncAttributeMaxDynamicSharedMemorySize, SMEM1);
    cudaFuncSetAttribute(k5_gemm2, cudaFuncAttributeMaxDynamicSharedMemorySize, SMEM2);

    k1_gemm1<<<F / BN1, 256, SMEM1>>>(X, W1, B1);
    k2_reduce<<<NC, 128>>>();
    k3_carry<<<1, 128>>>();
    k4_apply<<<NC, 128>>>();
    k5_gemm2<<<F / BN2, 256, SMEM2>>>(W2, B2, out);
}

// round 3
// speedup vs baseline: 1.2719x; 1.2719x over previous
#include <cuda_runtime.h>
#include <math.h>

// Problem constants
#define F      65536      // frames
#define K1     512        // input len
#define MEM    128        // memory channels
#define CHUNK  64         // frames per chunk (== BN1)
#define NC     1024       // scan chunks (F/CHUNK)
#define NG     32         // carry groups
#define GS     32         // chunks per group
#define TSCAN  65535      // scan length (frames 0..65534)

// Scratch (no cudaMalloc allowed)
__device__ float g_a[(size_t)F * MEM];     // a[t][c] = left*right
__device__ float g_b[(size_t)F * MEM];     // b[t][c] = 1-left
__device__ float g_z[(size_t)F * MEM];     // z[t][c]
__device__ float g_SA[NC * MEM];           // inclusive chunk summaries
__device__ float g_SB[NC * MEM];
__device__ float g_PA[NC * MEM];           // within-group exclusive prefixes
__device__ float g_PB[NC * MEM];
__device__ float g_GA[NG * MEM];           // group summaries
__device__ float g_GB[NG * MEM];
__device__ float g_Cg[NG * MEM];           // carry state into each group

__device__ __forceinline__ float sigmoidf_(float x) {
    return 1.0f / (1.0f + __expf(-x));
}

// ---------------------------------------------------------------------------
// Kernel 1: h = sigmoid(W1 @ X + B1); a = h_l*h_r; b = 1-h_l  (frame-major)
// PLUS fused chunk-summary reduction (block tile == scan chunk of 64 frames).
// ---------------------------------------------------------------------------
#define BN1 64
#define BK1 64
#define SMEM1 ((BK1 * 256 + BK1 * BN1) * 4)   // 80 KB

__global__ __launch_bounds__(256) void k1_gemm1(
    const float* __restrict__ X,
    const float* __restrict__ W1,
    const float* __restrict__ B1)
{
    extern __shared__ float sm[];
    float* Wsm = sm;                 // [BK1][256]  (k-major, transposed)
    float* Xsm = sm + BK1 * 256;     // [BK1][BN1]

    const int tid = threadIdx.x;
    const int mi  = tid & 31;        // row group 0..31
    const int ni  = tid >> 5;        // frame group 0..7
    const int t0  = blockIdx.x * BN1;

    float acc[8][8];
    #pragma unroll
    for (int r = 0; r < 8; r++)
        #pragma unroll
        for (int n = 0; n < 8; n++) acc[r][n] = 0.0f;

    for (int kb = 0; kb < K1; kb += BK1) {
        // W tile: thread 'tid' loads its own W1 row -> conflict-free STS
        const float4* wp = (const float4*)(W1 + (size_t)tid * K1 + kb);
        #pragma unroll
        for (int i = 0; i < 16; i++) {
            float4 v = wp[i];
            Wsm[(i * 4 + 0) * 256 + tid] = v.x;
            Wsm[(i * 4 + 1) * 256 + tid] = v.y;
            Wsm[(i * 4 + 2) * 256 + tid] = v.z;
            Wsm[(i * 4 + 3) * 256 + tid] = v.w;
        }
        // X tile: coalesced float4 loads
        #pragma unroll
        for (int i = 0; i < 4; i++) {
            int f  = tid + (i << 8);
            int k  = f >> 4;
            int c4 = (f & 15) << 2;
            float4 v = *(const float4*)(X + (size_t)(kb + k) * F + t0 + c4);
            *(float4*)&Xsm[k * BN1 + c4] = v;
        }
        __syncthreads();

        #pragma unroll 8
        for (int k = 0; k < BK1; k++) {
            float4 wl = *(float4*)&Wsm[k * 256 + mi * 4];
            float4 wr = *(float4*)&Wsm[k * 256 + 128 + mi * 4];
            float4 x0 = *(float4*)&Xsm[k * BN1 + ni * 8];
            float4 x1 = *(float4*)&Xsm[k * BN1 + ni * 8 + 4];
            float wv[8] = {wl.x, wl.y, wl.z, wl.w, wr.x, wr.y, wr.z, wr.w};
            float xv[8] = {x0.x, x0.y, x0.z, x0.w, x1.x, x1.y, x1.z, x1.w};
            #pragma unroll
            for (int r = 0; r < 8; r++)
                #pragma unroll
                for (int n = 0; n < 8; n++)
                    acc[r][n] = fmaf(wv[r], xv[n], acc[r][n]);
        }
        __syncthreads();
    }

    // Epilogue: sigmoid + a/b, written frame-major. Overwrite acc with a/b:
    // acc[j][n] <- a (channel mi*4+j), acc[4+j][n] <- b.
    float bl[4], br[4];
    #pragma unroll
    for (int j = 0; j < 4; j++) {
        bl[j] = B1[mi * 4 + j];
        br[j] = B1[128 + mi * 4 + j];
    }
    #pragma unroll
    for (int n = 0; n < 8; n++) {
        int t = t0 + ni * 8 + n;
        float4 av, bv;
        float* ap = (float*)&av;
        float* bp = (float*)&bv;
        #pragma unroll
        for (int j = 0; j < 4; j++) {
            float hl = sigmoidf_(acc[j][n] + bl[j]);
            float hr = sigmoidf_(acc[4 + j][n] + br[j]);
            ap[j] = hl * hr;
            bp[j] = 1.0f - hl;
            acc[j][n]     = ap[j];
            acc[4 + j][n] = bp[j];
        }
        *(float4*)&g_a[(size_t)t * MEM + mi * 4] = av;
        *(float4*)&g_b[(size_t)t * MEM + mi * 4] = bv;
    }

    // Fused chunk-summary reduce: per-thread 8-frame segment compose,
    // then combine the 8 ni-segments via smem (reuse tile smem).
    float* segA = sm;            // [8][128]
    float* segB = sm + 8 * 128;  // [8][128]
    #pragma unroll
    for (int j = 0; j < 4; j++) {
        float A = 1.0f, B = 0.0f;
        #pragma unroll
        for (int n = 0; n < 8; n++) {
            int t = t0 + ni * 8 + n;
            if (t < TSCAN) {
                float a = acc[j][n];
                float b = acc[4 + j][n];
                B = fmaf(a, B, b);
                A *= a;
            }
        }
        segA[ni * 128 + mi * 4 + j] = A;
        segB[ni * 128 + mi * 4 + j] = B;
    }
    __syncthreads();
    if (tid < 128) {
        float A = 1.0f, B = 0.0f;
        #pragma unroll
        for (int s = 0; s < 8; s++) {
            float As = segA[s * 128 + tid];
            float Bs = segB[s * 128 + tid];
            B = fmaf(As, B, Bs);
            A *= As;
        }
        g_SA[blockIdx.x * MEM + tid] = A;
        g_SB[blockIdx.x * MEM + tid] = B;
    }
}

// ---------------------------------------------------------------------------
// Kernel 3a: within-group exclusive prefix over chunk summaries + group sums.
// ---------------------------------------------------------------------------
__global__ __launch_bounds__(128) void k3a_prefix()
{
    const int ch = threadIdx.x;
    const int g  = blockIdx.x;
    float A = 1.0f, B = 0.0f;
    #pragma unroll 4
    for (int s = 0; s < GS; s++) {
        int j = g * GS + s;
        g_PA[j * MEM + ch] = A;
        g_PB[j * MEM + ch] = B;
        float sa = g_SA[j * MEM + ch];
        float sb = g_SB[j * MEM + ch];
        B = fmaf(sa, B, sb);
        A *= sa;
    }
    g_GA[g * MEM + ch] = A;
    g_GB[g * MEM + ch] = B;
}

// ---------------------------------------------------------------------------
// Kernel 3b: sequential scan over 32 group summaries -> group carry states.
// ---------------------------------------------------------------------------
__global__ __launch_bounds__(128) void k3b_carry()
{
    const int ch = threadIdx.x;
    float C = 0.0f;
    #pragma unroll 4
    for (int g = 0; g < NG; g++) {
        g_Cg[g * MEM + ch] = C;
        C = fmaf(g_GA[g * MEM + ch], C, g_GB[g * MEM + ch]);
    }
}

// ---------------------------------------------------------------------------
// Kernel 4: apply carries, write z frame-major. Warp-per-chunk, float4/thread.
// z[0][:]=0, z[t+1][:]=bb_t. Grid = NC/4 blocks of 128 threads.
// ---------------------------------------------------------------------------
__global__ __launch_bounds__(128) void k4_apply()
{
    const int lane = threadIdx.x & 31;
    const int wid  = threadIdx.x >> 5;
    const int j    = blockIdx.x * 4 + wid;
    const int c4   = lane * 4;
    const int g    = j >> 5;

    float4 PA = *(const float4*)&g_PA[j * MEM + c4];
    float4 PB = *(const float4*)&g_PB[j * MEM + c4];
    float4 CG = *(const float4*)&g_Cg[g * MEM + c4];
    float4 B;
    B.x = fmaf(PA.x, CG.x, PB.x);
    B.y = fmaf(PA.y, CG.y, PB.y);
    B.z = fmaf(PA.z, CG.z, PB.z);
    B.w = fmaf(PA.w, CG.w, PB.w);

    if (j == 0) {
        float4 zz = make_float4(0.f, 0.f, 0.f, 0.f);
        *(float4*)&g_z[c4] = zz;
    }

    const int tb = j * CHUNK;
    #pragma unroll 4
    for (int f = 0; f < CHUNK; f++) {
        int t = tb + f;
        if (t < TSCAN) {
            float4 a = *(const float4*)&g_a[(size_t)t * MEM + c4];
            float4 b = *(const float4*)&g_b[(size_t)t * MEM + c4];
            B.x = fmaf(a.x, B.x, b.x);
            B.y = fmaf(a.y, B.y, b.y);
            B.z = fmaf(a.z, B.z, b.z);
            B.w = fmaf(a.w, B.w, b.w);
            *(float4*)&g_z[(size_t)(t + 1) * MEM + c4] = B;
        }
    }
}

// ---------------------------------------------------------------------------
// Kernel 5: out = 1 - sigmoid(W2 @ z + B2) = 1/(1+exp(v)).
// ---------------------------------------------------------------------------
#define BN2 64
#define SMEM2 ((128 * 256 + BN2 * 128) * 4)   // 160 KB

__global__ __launch_bounds__(256) void k5_gemm2(
    const float* __restrict__ W2,
    const float* __restrict__ B2,
    float* __restrict__ out)
{
    extern __shared__ float sm[];
    float* Wsm = sm;               // [128][256] transposed
    float* Zsm = sm + 128 * 256;   // [BN2][128] frame-major

    const int tid = threadIdx.x;
    const int mi  = tid & 31;
    const int ni  = tid >> 5;
    const int t0  = blockIdx.x * BN2;

    // W2: thread 'tid' loads its own row (conflict-free STS)
    const float4* wp = (const float4*)(W2 + (size_t)tid * MEM);
    #pragma unroll
    for (int i = 0; i < 32; i++) {
        float4 v = wp[i];
        Wsm[(i * 4 + 0) * 256 + tid] = v.x;
        Wsm[(i * 4 + 1) * 256 + tid] = v.y;
        Wsm[(i * 4 + 2) * 256 + tid] = v.z;
        Wsm[(i * 4 + 3) * 256 + tid] = v.w;
    }
    // z tile: coalesced
    #pragma unroll
    for (int i = 0; i < 8; i++) {
        int f  = tid + (i << 8);
        int n  = f >> 5;
        int c4 = (f & 31) << 2;
        float4 v = *(const float4*)(g_z + (size_t)(t0 + n) * MEM + c4);
        *(float4*)&Zsm[n * MEM + c4] = v;
    }
    __syncthreads();

    float acc[8][8];
    #pragma unroll
    for (int r = 0; r < 8; r++)
        #pragma unroll
        for (int n = 0; n < 8; n++) acc[r][n] = 0.0f;

    #pragma unroll 8
    for (int k = 0; k < MEM; k++) {
        float4 wl = *(float4*)&Wsm[k * 256 + mi * 4];
        float4 wr = *(float4*)&Wsm[k * 256 + 128 + mi * 4];
        float wv[8] = {wl.x, wl.y, wl.z, wl.w, wr.x, wr.y, wr.z, wr.w};
        #pragma unroll
        for (int n = 0; n < 8; n++) {
            float zv = Zsm[(ni * 8 + n) * MEM + k];   // warp-uniform broadcast
            #pragma unroll
            for (int r = 0; r < 8; r++)
                acc[r][n] = fmaf(wv[r], zv, acc[r][n]);
        }
    }

    // Epilogue: out = 1/(1+exp(acc + B2))
    #pragma unroll
    for (int rr = 0; rr < 8; rr++) {
        int r = (rr < 4) ? (mi * 4 + rr) : (128 + mi * 4 + (rr - 4));
        float b2 = B2[r];
        float4 o0, o1;
        float* o0p = (float*)&o0;
        float* o1p = (float*)&o1;
        #pragma unroll
        for (int n = 0; n < 4; n++)
            o0p[n] = 1.0f / (1.0f + __expf(acc[rr][n] + b2));
        #pragma unroll
        for (int n = 4; n < 8; n++)
            o1p[n - 4] = 1.0f / (1.0f + __expf(acc[rr][n] + b2));
        *(float4*)&out[(size_t)r * F + t0 + ni * 8]     = o0;
        *(float4*)&out[(size_t)r * F + t0 + ni * 8 + 4] = o1;
    }
}

// ---------------------------------------------------------------------------
extern "C" void kernel_launch(void* const* d_in, const int* in_sizes, int n_in,
                              void* d_out, int out_size)
{
    const float* X  = (const float*)d_in[0];  // (512, 65536)
    const float* W1 = (const float*)d_in[1];  // (256, 512)
    const float* B1 = (const float*)d_in[2];  // (256, 1)
    const float* W2 = (const float*)d_in[3];  // (256, 128)
    const float* B2 = (const float*)d_in[4];  // (256, 1)
    float* out = (float*)d_out;               // (256, 65536)

    cudaFuncSetAttribute(k1_gemm1, cudaFuncAttributeMaxDynamicSharedMemorySize, SMEM1);
    cudaFuncSetAttribute(k5_gemm2, cudaFuncAttributeMaxDynamicSharedMemorySize, SMEM2);

    k1_gemm1<<<F / BN1, 256, SMEM1>>>(X, W1, B1);
    k3a_prefix<<<NG, 128>>>();
    k3b_carry<<<1, 128>>>();
    k4_apply<<<NC / 4, 128>>>();
    k5_gemm2<<<F / BN2, 256, SMEM2>>>(W2, B2, out);
}

// round 4
// speedup vs baseline: 2.6808x; 2.1077x over previous
#include <cuda_runtime.h>
#include <math.h>
#include <stdint.h>

// Problem constants
#define F      65536
#define K1     512
#define MEM    128
#define CHUNK  64
#define NC     1024
#define NG     32
#define GS     32
#define TSCAN  65535

// Scratch
__device__ float g_a[(size_t)F * MEM];
__device__ float g_b[(size_t)F * MEM];
__device__ float g_z[(size_t)F * MEM];
__device__ float g_SA[NC * MEM];
__device__ float g_SB[NC * MEM];
__device__ float g_PA[NC * MEM];
__device__ float g_PB[NC * MEM];
__device__ float g_GA[NG * MEM];
__device__ float g_GB[NG * MEM];
__device__ float g_Cg[NG * MEM];

__device__ __forceinline__ float sigmoidf_(float x) {
    return 1.0f / (1.0f + __expf(-x));
}
__device__ __forceinline__ float tf32r(float x) {
    uint32_t r;
    asm("cvt.rna.tf32.f32 %0, %1;" : "=r"(r) : "f"(x));
    return __uint_as_float(r);
}
// D = A(16x8,row) * B(8x8,col) + D, tf32
__device__ __forceinline__ void mma8(float* c, const float* a, const float* b) {
    asm("mma.sync.aligned.m16n8k8.row.col.f32.tf32.tf32.f32 "
        "{%0,%1,%2,%3},{%4,%5,%6,%7},{%8,%9},{%0,%1,%2,%3};"
        : "+f"(c[0]), "+f"(c[1]), "+f"(c[2]), "+f"(c[3])
        : "r"(__float_as_uint(a[0])), "r"(__float_as_uint(a[1])),
          "r"(__float_as_uint(a[2])), "r"(__float_as_uint(a[3])),
          "r"(__float_as_uint(b[0])), "r"(__float_as_uint(b[1])));
}

// ---------------------------------------------------------------------------
// Kernel 1: tf32 tensor GEMM1 + sigmoid + a/b + fused chunk summaries.
// Block: 512 threads (16 warps), tile M=256 x N=128, BK=64.
// Warp (wm,wh): rows {wm*16..+15} U {128+wm*16..+15}, frames wh*64..+63.
// ---------------------------------------------------------------------------
#define BN1 128
#define BK1 64
#define WS1 68      // W smem stride: bank = 4*row + k  (conflict-free frags)
#define XS1 136     // X smem stride: bank = 8*k + n
#define SS1 129     // staging stride
#define SMEM1 (2 * 128 * SS1 * 4)   // 132096 B >= (256*WS1 + 64*XS1)*4

__global__ __launch_bounds__(512) void k1_gemm1(
    const float* __restrict__ X,
    const float* __restrict__ W1,
    const float* __restrict__ B1)
{
    extern __shared__ float sm[];
    float* Wsm = sm;                // [256][WS1]
    float* Xsm = sm + 256 * WS1;    // [BK1][XS1]

    const int tid  = threadIdx.x;
    const int lane = tid & 31;
    const int w    = tid >> 5;
    const int wm   = w & 7;
    const int wh   = w >> 3;
    const int t0   = blockIdx.x * BN1;
    const int g    = lane >> 2;     // 0..7
    const int q    = lane & 3;      // 0..3

    float cL[8][4], cR[8][4];
    #pragma unroll
    for (int nt = 0; nt < 8; nt++)
        #pragma unroll
        for (int j = 0; j < 4; j++) { cL[nt][j] = 0.f; cR[nt][j] = 0.f; }

    for (int kb = 0; kb < K1; kb += BK1) {
        // W tile [256][64] -> Wsm[row][k]
        {
            int k4 = (tid & 15) * 4;
            #pragma unroll
            for (int p = 0; p < 8; p++) {
                int row = (tid >> 4) + p * 32;
                float4 v = *(const float4*)(W1 + (size_t)row * K1 + kb + k4);
                Wsm[row * WS1 + k4 + 0] = tf32r(v.x);
                Wsm[row * WS1 + k4 + 1] = tf32r(v.y);
                Wsm[row * WS1 + k4 + 2] = tf32r(v.z);
                Wsm[row * WS1 + k4 + 3] = tf32r(v.w);
            }
        }
        // X tile [64][128] -> Xsm[k][t]
        {
            int t4 = (tid & 31) * 4;
            #pragma unroll
            for (int p = 0; p < 4; p++) {
                int row = (tid >> 5) + p * 16;
                float4 v = *(const float4*)(X + (size_t)(kb + row) * F + t0 + t4);
                Xsm[row * XS1 + t4 + 0] = tf32r(v.x);
                Xsm[row * XS1 + t4 + 1] = tf32r(v.y);
                Xsm[row * XS1 + t4 + 2] = tf32r(v.z);
                Xsm[row * XS1 + t4 + 3] = tf32r(v.w);
            }
        }
        __syncthreads();

        #pragma unroll
        for (int k8 = 0; k8 < 8; k8++) {
            const int kk = k8 * 8;
            float aL[4], aR[4];
            {
                int ab = (wm * 16 + g) * WS1 + kk + q;
                aL[0] = Wsm[ab];
                aL[1] = Wsm[ab + 8 * WS1];
                aL[2] = Wsm[ab + 4];
                aL[3] = Wsm[ab + 8 * WS1 + 4];
                int rb = ab + 128 * WS1;
                aR[0] = Wsm[rb];
                aR[1] = Wsm[rb + 8 * WS1];
                aR[2] = Wsm[rb + 4];
                aR[3] = Wsm[rb + 8 * WS1 + 4];
            }
            #pragma unroll
            for (int nt = 0; nt < 8; nt++) {
                float b[2];
                int bb = (kk + q) * XS1 + wh * 64 + nt * 8 + g;
                b[0] = Xsm[bb];
                b[1] = Xsm[bb + 4 * XS1];
                mma8(cL[nt], aL, b);
                mma8(cR[nt], aR, b);
            }
        }
        __syncthreads();
    }

    // Epilogue: sigmoid -> a,b into staging smem
    float* aS = sm;                 // [128][SS1]
    float* bS = sm + 128 * SS1;
    const int r0 = wm * 16 + g;
    float bl0 = B1[r0],       bl1 = B1[r0 + 8];
    float br0 = B1[128 + r0], br1 = B1[128 + r0 + 8];

    #pragma unroll
    for (int nt = 0; nt < 8; nt++) {
        #pragma unroll
        for (int j = 0; j < 4; j++) {
            int rowoff = (j >> 1) << 3;          // 0 or 8
            int row = r0 + rowoff;
            int f = wh * 64 + nt * 8 + q * 2 + (j & 1);
            float hl = sigmoidf_(cL[nt][j] + ((j >> 1) ? bl1 : bl0));
            float hr = sigmoidf_(cR[nt][j] + ((j >> 1) ? br1 : br0));
            aS[f * SS1 + row] = hl * hr;
            bS[f * SS1 + row] = 1.0f - hl;
        }
    }
    __syncthreads();

    // Coalesced global stores of a,b
    #pragma unroll
    for (int i = 0; i < 32; i++) {
        int e = tid + i * 512;       // 0..16383
        int f = e >> 7, c = e & 127;
        g_a[(size_t)(t0 + f) * MEM + c] = aS[f * SS1 + c];
        g_b[(size_t)(t0 + f) * MEM + c] = bS[f * SS1 + c];
    }

    // Fused chunk summaries (2 chunks of 64 frames per block)
    if (tid < 256) {
        int ch = tid & 127, half = tid >> 7;
        int tb = t0 + half * 64;
        float A = 1.0f, B = 0.0f;
        #pragma unroll
        for (int f2 = 0; f2 < 64; f2++) {
            if (tb + f2 < TSCAN) {
                int fl = half * 64 + f2;
                float a = aS[fl * SS1 + ch];
                float b = bS[fl * SS1 + ch];
                B = fmaf(a, B, b);
                A *= a;
            }
        }
        g_SA[(blockIdx.x * 2 + half) * MEM + ch] = A;
        g_SB[(blockIdx.x * 2 + half) * MEM + ch] = B;
    }
}

// ---------------------------------------------------------------------------
// Kernel 3a: within-group exclusive prefix over chunk summaries + group sums.
// ---------------------------------------------------------------------------
__global__ __launch_bounds__(128) void k3a_prefix()
{
    const int ch = threadIdx.x;
    const int gg = blockIdx.x;
    float A = 1.0f, B = 0.0f;
    #pragma unroll 4
    for (int s = 0; s < GS; s++) {
        int j = gg * GS + s;
        g_PA[j * MEM + ch] = A;
        g_PB[j * MEM + ch] = B;
        float sa = g_SA[j * MEM + ch];
        float sb = g_SB[j * MEM + ch];
        B = fmaf(sa, B, sb);
        A *= sa;
    }
    g_GA[gg * MEM + ch] = A;
    g_GB[gg * MEM + ch] = B;
}

__global__ __launch_bounds__(128) void k3b_carry()
{
    const int ch = threadIdx.x;
    float C = 0.0f;
    #pragma unroll 4
    for (int gg = 0; gg < NG; gg++) {
        g_Cg[gg * MEM + ch] = C;
        C = fmaf(g_GA[gg * MEM + ch], C, g_GB[gg * MEM + ch]);
    }
}

// ---------------------------------------------------------------------------
// Kernel 4: apply carries, write z frame-major. Warp-per-chunk, float4/thread.
// ---------------------------------------------------------------------------
__global__ __launch_bounds__(128) void k4_apply()
{
    const int lane = threadIdx.x & 31;
    const int wid  = threadIdx.x >> 5;
    const int j    = blockIdx.x * 4 + wid;
    const int c4   = lane * 4;
    const int gg   = j >> 5;

    float4 PA = *(const float4*)&g_PA[j * MEM + c4];
    float4 PB = *(const float4*)&g_PB[j * MEM + c4];
    float4 CG = *(const float4*)&g_Cg[gg * MEM + c4];
    float4 B;
    B.x = fmaf(PA.x, CG.x, PB.x);
    B.y = fmaf(PA.y, CG.y, PB.y);
    B.z = fmaf(PA.z, CG.z, PB.z);
    B.w = fmaf(PA.w, CG.w, PB.w);

    if (j == 0) {
        float4 zz = make_float4(0.f, 0.f, 0.f, 0.f);
        *(float4*)&g_z[c4] = zz;
    }

    const int tb = j * CHUNK;
    #pragma unroll 4
    for (int f = 0; f < CHUNK; f++) {
        int t = tb + f;
        if (t < TSCAN) {
            float4 a = *(const float4*)&g_a[(size_t)t * MEM + c4];
            float4 b = *(const float4*)&g_b[(size_t)t * MEM + c4];
            B.x = fmaf(a.x, B.x, b.x);
            B.y = fmaf(a.y, B.y, b.y);
            B.z = fmaf(a.z, B.z, b.z);
            B.w = fmaf(a.w, B.w, b.w);
            *(float4*)&g_z[(size_t)(t + 1) * MEM + c4] = B;
        }
    }
}

// ---------------------------------------------------------------------------
// Kernel 5: tf32 tensor GEMM2: out = 1/(1+exp(W2 @ z + B2)).
// Block: 256 threads (8 warps), tile M=256 x N=64, K=128 resident.
// ---------------------------------------------------------------------------
#define BN2 64
#define WS2 132     // W2 stride: bank = 4*row + k
#define ZS2 132     // z tile [f][ZS2]: B-frag bank = 4*g + q (conflict-free)
#define SMEM2 ((256 * WS2 + 64 * ZS2) * 4)   // 168960

__global__ __launch_bounds__(256) void k5_gemm2(
    const float* __restrict__ W2,
    const float* __restrict__ B2,
    float* __restrict__ out)
{
    extern __shared__ float sm[];
    float* Wsm = sm;                // [256][WS2]
    float* Zsm = sm + 256 * WS2;    // [64][ZS2]

    const int tid  = threadIdx.x;
    const int lane = tid & 31;
    const int w    = tid >> 5;      // 0..7
    const int t0   = blockIdx.x * BN2;
    const int g    = lane >> 2;
    const int q    = lane & 3;

    // W2 [256][128] -> Wsm[row][k]
    {
        int k4 = lane * 4;
        #pragma unroll
        for (int p = 0; p < 32; p++) {
            int row = w + p * 8;
            float4 v = *(const float4*)(W2 + (size_t)row * MEM + k4);
            Wsm[row * WS2 + k4 + 0] = tf32r(v.x);
            Wsm[row * WS2 + k4 + 1] = tf32r(v.y);
            Wsm[row * WS2 + k4 + 2] = tf32r(v.z);
            Wsm[row * WS2 + k4 + 3] = tf32r(v.w);
        }
    }
    // z tile [64][128] coalesced -> Zsm[f][c]
    #pragma unroll
    for (int i = 0; i < 8; i++) {
        int idx = i * 256 + tid;     // float4 index
        int f   = idx >> 5;
        int c4  = (idx & 31) * 4;
        float4 v = *(const float4*)(g_z + (size_t)(t0 + f) * MEM + c4);
        float4 o;
        o.x = tf32r(v.x); o.y = tf32r(v.y); o.z = tf32r(v.z); o.w = tf32r(v.w);
        *(float4*)&Zsm[f * ZS2 + c4] = o;
    }
    __syncthreads();

    float cL[8][4], cR[8][4];
    #pragma unroll
    for (int nt = 0; nt < 8; nt++)
        #pragma unroll
        for (int j = 0; j < 4; j++) { cL[nt][j] = 0.f; cR[nt][j] = 0.f; }

    #pragma unroll
    for (int k8 = 0; k8 < 16; k8++) {
        const int kk = k8 * 8;
        float aL[4], aR[4];
        {
            int ab = (w * 16 + g) * WS2 + kk + q;
            aL[0] = Wsm[ab];
            aL[1] = Wsm[ab + 8 * WS2];
            aL[2] = Wsm[ab + 4];
            aL[3] = Wsm[ab + 8 * WS2 + 4];
            int rb = ab + 128 * WS2;
            aR[0] = Wsm[rb];
            aR[1] = Wsm[rb + 8 * WS2];
            aR[2] = Wsm[rb + 4];
            aR[3] = Wsm[rb + 8 * WS2 + 4];
        }
        #pragma unroll
        for (int nt = 0; nt < 8; nt++) {
            float b[2];
            // b0: (k = kk+q, n = nt*8+g) from Zsm[n][k]
            int bb = (nt * 8 + g) * ZS2 + kk + q;
            b[0] = Zsm[bb];
            b[1] = Zsm[bb + 4];
            mma8(cL[nt], aL, b);
            mma8(cR[nt], aR, b);
        }
    }

    // Epilogue: out = 1/(1+exp(v + B2)), float2 stores (32B sectors/4 lanes)
    const int r0 = w * 16 + g;
    float bL0 = B2[r0],       bL1 = B2[r0 + 8];
    float bR0 = B2[128 + r0], bR1 = B2[128 + r0 + 8];

    #pragma unroll
    for (int nt = 0; nt < 8; nt++) {
        int t = t0 + nt * 8 + q * 2;
        float2 o;
        o.x = 1.0f / (1.0f + __expf(cL[nt][0] + bL0));
        o.y = 1.0f / (1.0f + __expf(cL[nt][1] + bL0));
        *(float2*)&out[(size_t)r0 * F + t] = o;
        o.x = 1.0f / (1.0f + __expf(cL[nt][2] + bL1));
        o.y = 1.0f / (1.0f + __expf(cL[nt][3] + bL1));
        *(float2*)&out[(size_t)(r0 + 8) * F + t] = o;
        o.x = 1.0f / (1.0f + __expf(cR[nt][0] + bR0));
        o.y = 1.0f / (1.0f + __expf(cR[nt][1] + bR0));
        *(float2*)&out[(size_t)(128 + r0) * F + t] = o;
        o.x = 1.0f / (1.0f + __expf(cR[nt][2] + bR1));
        o.y = 1.0f / (1.0f + __expf(cR[nt][3] + bR1));
        *(float2*)&out[(size_t)(128 + r0 + 8) * F + t] = o;
    }
}

// ---------------------------------------------------------------------------
extern "C" void kernel_launch(void* const* d_in, const int* in_sizes, int n_in,
                              void* d_out, int out_size)
{
    const float* X  = (const float*)d_in[0];  // (512, 65536)
    const float* W1 = (const float*)d_in[1];  // (256, 512)
    const float* B1 = (const float*)d_in[2];  // (256, 1)
    const float* W2 = (const float*)d_in[3];  // (256, 128)
    const float* B2 = (const float*)d_in[4];  // (256, 1)
    float* out = (float*)d_out;               // (256, 65536)

    cudaFuncSetAttribute(k1_gemm1, cudaFuncAttributeMaxDynamicSharedMemorySize, SMEM1);
    cudaFuncSetAttribute(k5_gemm2, cudaFuncAttributeMaxDynamicSharedMemorySize, SMEM2);

    k1_gemm1<<<F / BN1, 512, SMEM1>>>(X, W1, B1);
    k3a_prefix<<<NG, 128>>>();
    k3b_carry<<<1, 128>>>();
    k4_apply<<<NC / 4, 128>>>();
    k5_gemm2<<<F / BN2, 256, SMEM2>>>(W2, B2, out);
}

// round 5
// speedup vs baseline: 3.1782x; 1.1855x over previous
#include <cuda_runtime.h>
#include <cuda_fp16.h>
#include <math.h>
#include <stdint.h>

// Problem constants
#define F      65536
#define K1     512
#define MEM    128
#define CHUNK  64
#define NC     1024
#define NG     32
#define GS     32
#define TSCAN  65535

// Scratch
__device__ __align__(128) __half g_ah[(size_t)F * MEM];
__device__ __align__(128) __half g_bh[(size_t)F * MEM];
__device__ float g_SA[NC * MEM];
__device__ float g_SB[NC * MEM];
__device__ float g_PA[NC * MEM];
__device__ float g_PB[NC * MEM];
__device__ float g_GA[NG * MEM];
__device__ float g_GB[NG * MEM];
__device__ float g_Cg[NG * MEM];

__device__ __forceinline__ float sigmoidf_(float x) {
    return 1.0f / (1.0f + __expf(-x));
}
__device__ __forceinline__ float tf32r(float x) {
    uint32_t r;
    asm("cvt.rna.tf32.f32 %0, %1;" : "=r"(r) : "f"(x));
    return __uint_as_float(r);
}
__device__ __forceinline__ void mma8(float* c, const float* a, const float* b) {
    asm("mma.sync.aligned.m16n8k8.row.col.f32.tf32.tf32.f32 "
        "{%0,%1,%2,%3},{%4,%5,%6,%7},{%8,%9},{%0,%1,%2,%3};"
        : "+f"(c[0]), "+f"(c[1]), "+f"(c[2]), "+f"(c[3])
        : "r"(__float_as_uint(a[0])), "r"(__float_as_uint(a[1])),
          "r"(__float_as_uint(a[2])), "r"(__float_as_uint(a[3])),
          "r"(__float_as_uint(b[0])), "r"(__float_as_uint(b[1])));
}
__device__ __forceinline__ void cpa16(void* dst, const void* src) {
    uint32_t d = (uint32_t)__cvta_generic_to_shared(dst);
    asm volatile("cp.async.cg.shared.global [%0], [%1], 16;" :: "r"(d), "l"(src));
}

// ---------------------------------------------------------------------------
// Kernel 1: tf32 tensor GEMM1 (cp.async double-buffered) + sigmoid + a/b(fp16)
// + fused chunk summaries. 512 threads, tile M=256 x N=128, BK=32, 16 stages.
// ---------------------------------------------------------------------------
#define BN1 128
#define BK1 32
#define WS1 36      // bank = (4*row + k) & 31  -> conflict-free A frags
#define XS1 136     // bank = (8*k + t) & 31    -> conflict-free B frags
#define WT1 (256 * WS1)
#define XT1 (BK1 * XS1)
#define SSH 136     // half staging stride (even -> half2-aligned readback)
#define SMEM1 (2 * (WT1 + XT1) * 4)   // 108544 B

__global__ __launch_bounds__(512) void k1_gemm1(
    const float* __restrict__ X,
    const float* __restrict__ W1,
    const float* __restrict__ B1)
{
    extern __shared__ float sm[];

    const int tid  = threadIdx.x;
    const int lane = tid & 31;
    const int w    = tid >> 5;
    const int wm   = w & 7;
    const int wh   = w >> 3;
    const int t0   = blockIdx.x * BN1;
    const int g    = lane >> 2;
    const int q    = lane & 3;

    float cL[8][4], cR[8][4];
    #pragma unroll
    for (int nt = 0; nt < 8; nt++)
        #pragma unroll
        for (int j = 0; j < 4; j++) { cL[nt][j] = 0.f; cR[nt][j] = 0.f; }

    // prefetch of one BK=32 stage into buffer s
    auto prefetch = [&](int s, int kb) {
        float* Wd = sm + s * (WT1 + XT1);
        float* Xd = Wd + WT1;
        #pragma unroll
        for (int p = 0; p < 4; p++) {            // W: 256x32 = 2048 float4
            int idx = tid + p * 512;
            int row = idx >> 3, c4 = (idx & 7) * 4;
            cpa16(Wd + row * WS1 + c4, W1 + (size_t)row * K1 + kb + c4);
        }
        #pragma unroll
        for (int p = 0; p < 2; p++) {            // X: 32x128 = 1024 float4
            int idx = tid + p * 512;
            int k = idx >> 5, t4 = (idx & 31) * 4;
            cpa16(Xd + k * XS1 + t4, X + (size_t)(kb + k) * F + t0 + t4);
        }
        asm volatile("cp.async.commit_group;");
    };

    prefetch(0, 0);
    for (int it = 0; it < 16; it++) {
        if (it < 15) {
            prefetch((it + 1) & 1, (it + 1) * BK1);
            asm volatile("cp.async.wait_group 1;");
        } else {
            asm volatile("cp.async.wait_group 0;");
        }
        __syncthreads();

        const float* Wsm = sm + (it & 1) * (WT1 + XT1);
        const float* Xsm = Wsm + WT1;
        #pragma unroll
        for (int k8 = 0; k8 < 4; k8++) {
            const int kk = k8 * 8;
            float aL[4], aR[4];
            {
                int ab = (wm * 16 + g) * WS1 + kk + q;
                aL[0] = Wsm[ab];
                aL[1] = Wsm[ab + 8 * WS1];
                aL[2] = Wsm[ab + 4];
                aL[3] = Wsm[ab + 8 * WS1 + 4];
                int rb = ab + 128 * WS1;
                aR[0] = Wsm[rb];
                aR[1] = Wsm[rb + 8 * WS1];
                aR[2] = Wsm[rb + 4];
                aR[3] = Wsm[rb + 8 * WS1 + 4];
            }
            #pragma unroll
            for (int nt = 0; nt < 8; nt++) {
                float b[2];
                int bb = (kk + q) * XS1 + wh * 64 + nt * 8 + g;
                b[0] = Xsm[bb];
                b[1] = Xsm[bb + 4 * XS1];
                mma8(cL[nt], aL, b);
                mma8(cR[nt], aR, b);
            }
        }
        __syncthreads();
    }

    // Epilogue: sigmoid -> a,b (fp16) into staging smem (reuse tile smem)
    __half* aS = (__half*)sm;            // [128][SSH]
    __half* bS = aS + 128 * SSH;
    const int r0 = wm * 16 + g;
    float bl0 = B1[r0],       bl1 = B1[r0 + 8];
    float br0 = B1[128 + r0], br1 = B1[128 + r0 + 8];

    #pragma unroll
    for (int nt = 0; nt < 8; nt++) {
        #pragma unroll
        for (int j = 0; j < 4; j++) {
            int row = r0 + ((j >> 1) << 3);
            int f = wh * 64 + nt * 8 + q * 2 + (j & 1);
            float hl = sigmoidf_(cL[nt][j] + ((j >> 1) ? bl1 : bl0));
            float hr = sigmoidf_(cR[nt][j] + ((j >> 1) ? br1 : br0));
            aS[f * SSH + row] = __float2half(hl * hr);
            bS[f * SSH + row] = __float2half(1.0f - hl);
        }
    }
    __syncthreads();

    // Coalesced half2 global stores
    #pragma unroll
    for (int i = 0; i < 16; i++) {
        int e2 = tid + i * 512;          // 0..8191
        int f = e2 >> 6, c = e2 & 63;
        __half2 va = *(__half2*)&aS[f * SSH + 2 * c];
        __half2 vb = *(__half2*)&bS[f * SSH + 2 * c];
        *(__half2*)&g_ah[(size_t)(t0 + f) * MEM + 2 * c] = va;
        *(__half2*)&g_bh[(size_t)(t0 + f) * MEM + 2 * c] = vb;
    }

    // Fused chunk summaries (2 chunks of 64 frames), from the ROUNDED values
    if (tid < 256) {
        int ch = tid & 127, hf = tid >> 7;
        int tb = t0 + hf * 64;
        float A = 1.0f, B = 0.0f;
        #pragma unroll 8
        for (int f2 = 0; f2 < 64; f2++) {
            if (tb + f2 < TSCAN) {
                int fl = hf * 64 + f2;
                float a = __half2float(aS[fl * SSH + ch]);
                float b = __half2float(bS[fl * SSH + ch]);
                B = fmaf(a, B, b);
                A *= a;
            }
        }
        g_SA[(blockIdx.x * 2 + hf) * MEM + ch] = A;
        g_SB[(blockIdx.x * 2 + hf) * MEM + ch] = B;
    }
}

// ---------------------------------------------------------------------------
// Kernel 3a/3b: carry hierarchy (unchanged)
// ---------------------------------------------------------------------------
__global__ __launch_bounds__(128) void k3a_prefix()
{
    const int ch = threadIdx.x;
    const int gg = blockIdx.x;
    float A = 1.0f, B = 0.0f;
    #pragma unroll 4
    for (int s = 0; s < GS; s++) {
        int j = gg * GS + s;
        g_PA[j * MEM + ch] = A;
        g_PB[j * MEM + ch] = B;
        float sa = g_SA[j * MEM + ch];
        float sb = g_SB[j * MEM + ch];
        B = fmaf(sa, B, sb);
        A *= sa;
    }
    g_GA[gg * MEM + ch] = A;
    g_GB[gg * MEM + ch] = B;
}

__global__ __launch_bounds__(128) void k3b_carry()
{
    const int ch = threadIdx.x;
    float C = 0.0f;
    #pragma unroll 4
    for (int gg = 0; gg < NG; gg++) {
        g_Cg[gg * MEM + ch] = C;
        C = fmaf(g_GA[gg * MEM + ch], C, g_GB[gg * MEM + ch]);
    }
}

// ---------------------------------------------------------------------------
// Kernel 5 (FUSED): per-chunk scan replay -> z tile in SMEM -> tf32 GEMM2
// -> out = 1/(1+exp(v+B2)). Block = chunk j = 64 frames, 256 threads.
// ---------------------------------------------------------------------------
#define BN2 64
#define WS2 132
#define ZS2 132
#define SMEM5 ((256 * WS2 + BN2 * ZS2) * 4 + 2 * BN2 * MEM * 2)  // 201728 B

__global__ __launch_bounds__(256) void k5_fused(
    const float* __restrict__ W2,
    const float* __restrict__ B2,
    float* __restrict__ out)
{
    extern __shared__ float sm[];
    float* Wsm = sm;                       // [256][WS2]
    float* Zsm = sm + 256 * WS2;           // [64][ZS2]
    __half* aT = (__half*)(Zsm + BN2 * ZS2);  // [64][128]
    __half* bT = aT + BN2 * MEM;

    const int tid  = threadIdx.x;
    const int lane = tid & 31;
    const int w    = tid >> 5;
    const int j    = blockIdx.x;           // chunk index
    const int t0   = j * BN2;
    const int g    = lane >> 2;
    const int q    = lane & 3;

    // a,b tile: coalesced half2 loads
    #pragma unroll
    for (int i = 0; i < 16; i++) {
        int e2 = tid + i * 256;            // 0..4095
        int f = e2 >> 6, c = e2 & 63;
        *(__half2*)&aT[f * MEM + 2 * c] = *(const __half2*)&g_ah[(size_t)(t0 + f) * MEM + 2 * c];
        *(__half2*)&bT[f * MEM + 2 * c] = *(const __half2*)&g_bh[(size_t)(t0 + f) * MEM + 2 * c];
    }
    __syncthreads();

    // Scan replay (warps 0-3) — warps 4-7 proceed to W2 loads meanwhile
    if (tid < 128) {
        const int ch = tid;
        const int gg = j >> 5;
        float B = fmaf(g_PA[j * MEM + ch], g_Cg[gg * MEM + ch], g_PB[j * MEM + ch]);
        #pragma unroll 8
        for (int f = 0; f < BN2; f++) {
            Zsm[f * ZS2 + ch] = tf32r(B);
            float a = __half2float(aT[f * MEM + ch]);
            float b = __half2float(bT[f * MEM + ch]);
            B = fmaf(a, B, b);
        }
    }

    // W2 [256][128] -> Wsm[row][k] (one row per warp per step)
    {
        int k4 = lane * 4;
        #pragma unroll
        for (int p = 0; p < 32; p++) {
            int row = w + p * 8;
            float4 v = *(const float4*)(W2 + (size_t)row * MEM + k4);
            Wsm[row * WS2 + k4 + 0] = tf32r(v.x);
            Wsm[row * WS2 + k4 + 1] = tf32r(v.y);
            Wsm[row * WS2 + k4 + 2] = tf32r(v.z);
            Wsm[row * WS2 + k4 + 3] = tf32r(v.w);
        }
    }
    __syncthreads();

    float cL[8][4], cR[8][4];
    #pragma unroll
    for (int nt = 0; nt < 8; nt++)
        #pragma unroll
        for (int jj = 0; jj < 4; jj++) { cL[nt][jj] = 0.f; cR[nt][jj] = 0.f; }

    #pragma unroll
    for (int k8 = 0; k8 < 16; k8++) {
        const int kk = k8 * 8;
        float aL[4], aR[4];
        {
            int ab = (w * 16 + g) * WS2 + kk + q;
            aL[0] = Wsm[ab];
            aL[1] = Wsm[ab + 8 * WS2];
            aL[2] = Wsm[ab + 4];
            aL[3] = Wsm[ab + 8 * WS2 + 4];
            int rb = ab + 128 * WS2;
            aR[0] = Wsm[rb];
            aR[1] = Wsm[rb + 8 * WS2];
            aR[2] = Wsm[rb + 4];
            aR[3] = Wsm[rb + 8 * WS2 + 4];
        }
        #pragma unroll
        for (int nt = 0; nt < 8; nt++) {
            float b[2];
            int bb = (nt * 8 + g) * ZS2 + kk + q;
            b[0] = Zsm[bb];
            b[1] = Zsm[bb + 4];
            mma8(cL[nt], aL, b);
            mma8(cR[nt], aR, b);
        }
    }

    // Epilogue: out = 1/(1+exp(v + B2)), float2 stores
    const int r0 = w * 16 + g;
    float bL0 = B2[r0],       bL1 = B2[r0 + 8];
    float bR0 = B2[128 + r0], bR1 = B2[128 + r0 + 8];

    #pragma unroll
    for (int nt = 0; nt < 8; nt++) {
        int t = t0 + nt * 8 + q * 2;
        float2 o;
        o.x = 1.0f / (1.0f + __expf(cL[nt][0] + bL0));
        o.y = 1.0f / (1.0f + __expf(cL[nt][1] + bL0));
        *(float2*)&out[(size_t)r0 * F + t] = o;
        o.x = 1.0f / (1.0f + __expf(cL[nt][2] + bL1));
        o.y = 1.0f / (1.0f + __expf(cL[nt][3] + bL1));
        *(float2*)&out[(size_t)(r0 + 8) * F + t] = o;
        o.x = 1.0f / (1.0f + __expf(cR[nt][0] + bR0));
        o.y = 1.0f / (1.0f + __expf(cR[nt][1] + bR0));
        *(float2*)&out[(size_t)(128 + r0) * F + t] = o;
        o.x = 1.0f / (1.0f + __expf(cR[nt][2] + bR1));
        o.y = 1.0f / (1.0f + __expf(cR[nt][3] + bR1));
        *(float2*)&out[(size_t)(128 + r0 + 8) * F + t] = o;
    }
}

// ---------------------------------------------------------------------------
extern "C" void kernel_launch(void* const* d_in, const int* in_sizes, int n_in,
                              void* d_out, int out_size)
{
    const float* X  = (const float*)d_in[0];  // (512, 65536)
    const float* W1 = (const float*)d_in[1];  // (256, 512)
    const float* B1 = (const float*)d_in[2];  // (256, 1)
    const float* W2 = (const float*)d_in[3];  // (256, 128)
    const float* B2 = (const float*)d_in[4];  // (256, 1)
    float* out = (float*)d_out;               // (256, 65536)

    cudaFuncSetAttribute(k1_gemm1, cudaFuncAttributeMaxDynamicSharedMemorySize, SMEM1);
    cudaFuncSetAttribute(k5_fused, cudaFuncAttributeMaxDynamicSharedMemorySize, SMEM5);

    k1_gemm1<<<F / BN1, 512, SMEM1>>>(X, W1, B1);
    k3a_prefix<<<NG, 128>>>();
    k3b_carry<<<1, 128>>>();
    k5_fused<<<NC, 256, SMEM5>>>(W2, B2, out);
}

// round 6
// speedup vs baseline: 3.2222x; 1.0139x over previous
#include <cuda_runtime.h>
#include <cuda_fp16.h>
#include <math.h>
#include <stdint.h>

// Problem constants
#define F      65536
#define K1     512
#define MEM    128
#define CHUNK  64
#define NC     1024
#define NG     32
#define GS     32
#define TSCAN  65535

// Scratch
__device__ __align__(128) __half g_ah[(size_t)F * MEM];
__device__ __align__(128) __half g_bh[(size_t)F * MEM];
__device__ float g_SA[NC * MEM];
__device__ float g_SB[NC * MEM];
__device__ float g_PA[NC * MEM];
__device__ float g_PB[NC * MEM];
__device__ float g_GA[NG * MEM];
__device__ float g_GB[NG * MEM];
__device__ float g_Cg[NG * MEM];

__device__ __forceinline__ float sigmoidf_(float x) {
    return 1.0f / (1.0f + __expf(-x));
}
__device__ __forceinline__ float tf32r(float x) {
    uint32_t r;
    asm("cvt.rna.tf32.f32 %0, %1;" : "=r"(r) : "f"(x));
    return __uint_as_float(r);
}
__device__ __forceinline__ void mma8(float* c, const float* a, const float* b) {
    asm("mma.sync.aligned.m16n8k8.row.col.f32.tf32.tf32.f32 "
        "{%0,%1,%2,%3},{%4,%5,%6,%7},{%8,%9},{%0,%1,%2,%3};"
        : "+f"(c[0]), "+f"(c[1]), "+f"(c[2]), "+f"(c[3])
        : "r"(__float_as_uint(a[0])), "r"(__float_as_uint(a[1])),
          "r"(__float_as_uint(a[2])), "r"(__float_as_uint(a[3])),
          "r"(__float_as_uint(b[0])), "r"(__float_as_uint(b[1])));
}
__device__ __forceinline__ void cpa16(void* dst, const void* src) {
    uint32_t d = (uint32_t)__cvta_generic_to_shared(dst);
    asm volatile("cp.async.cg.shared.global [%0], [%1], 16;" :: "r"(d), "l"(src));
}

// ---------------------------------------------------------------------------
// Kernel 1: tf32 tensor GEMM1 (cp.async double-buffered) + sigmoid + a/b(fp16)
// + fused chunk summaries. 512 threads, tile M=256 x N=128, BK=32, 16 stages.
// ---------------------------------------------------------------------------
#define BN1 128
#define BK1 32
#define WS1 36      // bank = (4*row + k) & 31  -> conflict-free A frags
#define XS1 136     // bank = (8*k + t) & 31    -> conflict-free B frags
#define WT1 (256 * WS1)
#define XT1 (BK1 * XS1)
#define SSH 136     // half staging stride (even -> half2-aligned readback)
#define SMEM1 (2 * (WT1 + XT1) * 4)   // 108544 B

__global__ __launch_bounds__(512) void k1_gemm1(
    const float* __restrict__ X,
    const float* __restrict__ W1,
    const float* __restrict__ B1)
{
    extern __shared__ float sm[];

    const int tid  = threadIdx.x;
    const int lane = tid & 31;
    const int w    = tid >> 5;
    const int wm   = w & 7;
    const int wh   = w >> 3;
    const int t0   = blockIdx.x * BN1;
    const int g    = lane >> 2;
    const int q    = lane & 3;

    float cL[8][4], cR[8][4];
    #pragma unroll
    for (int nt = 0; nt < 8; nt++)
        #pragma unroll
        for (int j = 0; j < 4; j++) { cL[nt][j] = 0.f; cR[nt][j] = 0.f; }

    auto prefetch = [&](int s, int kb) {
        float* Wd = sm + s * (WT1 + XT1);
        float* Xd = Wd + WT1;
        #pragma unroll
        for (int p = 0; p < 4; p++) {            // W: 256x32 = 2048 float4
            int idx = tid + p * 512;
            int row = idx >> 3, c4 = (idx & 7) * 4;
            cpa16(Wd + row * WS1 + c4, W1 + (size_t)row * K1 + kb + c4);
        }
        #pragma unroll
        for (int p = 0; p < 2; p++) {            // X: 32x128 = 1024 float4
            int idx = tid + p * 512;
            int k = idx >> 5, t4 = (idx & 31) * 4;
            cpa16(Xd + k * XS1 + t4, X + (size_t)(kb + k) * F + t0 + t4);
        }
        asm volatile("cp.async.commit_group;");
    };

    prefetch(0, 0);
    for (int it = 0; it < 16; it++) {
        if (it < 15) {
            prefetch((it + 1) & 1, (it + 1) * BK1);
            asm volatile("cp.async.wait_group 1;");
        } else {
            asm volatile("cp.async.wait_group 0;");
        }
        __syncthreads();

        const float* Wsm = sm + (it & 1) * (WT1 + XT1);
        const float* Xsm = Wsm + WT1;
        #pragma unroll
        for (int k8 = 0; k8 < 4; k8++) {
            const int kk = k8 * 8;
            float aL[4], aR[4];
            {
                int ab = (wm * 16 + g) * WS1 + kk + q;
                aL[0] = Wsm[ab];
                aL[1] = Wsm[ab + 8 * WS1];
                aL[2] = Wsm[ab + 4];
                aL[3] = Wsm[ab + 8 * WS1 + 4];
                int rb = ab + 128 * WS1;
                aR[0] = Wsm[rb];
                aR[1] = Wsm[rb + 8 * WS1];
                aR[2] = Wsm[rb + 4];
                aR[3] = Wsm[rb + 8 * WS1 + 4];
            }
            #pragma unroll
            for (int nt = 0; nt < 8; nt++) {
                float b[2];
                int bb = (kk + q) * XS1 + wh * 64 + nt * 8 + g;
                b[0] = Xsm[bb];
                b[1] = Xsm[bb + 4 * XS1];
                mma8(cL[nt], aL, b);
                mma8(cR[nt], aR, b);
            }
        }
        __syncthreads();
    }

    // Epilogue: sigmoid -> a,b (fp16) into staging smem (reuse tile smem)
    __half* aS = (__half*)sm;            // [128][SSH]
    __half* bS = aS + 128 * SSH;
    const int r0 = wm * 16 + g;
    float bl0 = B1[r0],       bl1 = B1[r0 + 8];
    float br0 = B1[128 + r0], br1 = B1[128 + r0 + 8];

    #pragma unroll
    for (int nt = 0; nt < 8; nt++) {
        #pragma unroll
        for (int j = 0; j < 4; j++) {
            int row = r0 + ((j >> 1) << 3);
            int f = wh * 64 + nt * 8 + q * 2 + (j & 1);
            float hl = sigmoidf_(cL[nt][j] + ((j >> 1) ? bl1 : bl0));
            float hr = sigmoidf_(cR[nt][j] + ((j >> 1) ? br1 : br0));
            aS[f * SSH + row] = __float2half(hl * hr);
            bS[f * SSH + row] = __float2half(1.0f - hl);
        }
    }
    __syncthreads();

    // Coalesced half2 global stores
    #pragma unroll
    for (int i = 0; i < 16; i++) {
        int e2 = tid + i * 512;          // 0..8191
        int f = e2 >> 6, c = e2 & 63;
        __half2 va = *(__half2*)&aS[f * SSH + 2 * c];
        __half2 vb = *(__half2*)&bS[f * SSH + 2 * c];
        *(__half2*)&g_ah[(size_t)(t0 + f) * MEM + 2 * c] = va;
        *(__half2*)&g_bh[(size_t)(t0 + f) * MEM + 2 * c] = vb;
    }

    // Fused chunk summaries (2 chunks of 64 frames), from the ROUNDED values
    if (tid < 256) {
        int ch = tid & 127, hf = tid >> 7;
        int tb = t0 + hf * 64;
        float A = 1.0f, B = 0.0f;
        #pragma unroll 8
        for (int f2 = 0; f2 < 64; f2++) {
            if (tb + f2 < TSCAN) {
                int fl = hf * 64 + f2;
                float a = __half2float(aS[fl * SSH + ch]);
                float b = __half2float(bS[fl * SSH + ch]);
                B = fmaf(a, B, b);
                A *= a;
            }
        }
        g_SA[(blockIdx.x * 2 + hf) * MEM + ch] = A;
        g_SB[(blockIdx.x * 2 + hf) * MEM + ch] = B;
    }
}

// ---------------------------------------------------------------------------
// Kernel 3a/3b: carry hierarchy
// ---------------------------------------------------------------------------
__global__ __launch_bounds__(128) void k3a_prefix()
{
    const int ch = threadIdx.x;
    const int gg = blockIdx.x;
    float A = 1.0f, B = 0.0f;
    #pragma unroll 4
    for (int s = 0; s < GS; s++) {
        int j = gg * GS + s;
        g_PA[j * MEM + ch] = A;
        g_PB[j * MEM + ch] = B;
        float sa = g_SA[j * MEM + ch];
        float sb = g_SB[j * MEM + ch];
        B = fmaf(sa, B, sb);
        A *= sa;
    }
    g_GA[gg * MEM + ch] = A;
    g_GB[gg * MEM + ch] = B;
}

__global__ __launch_bounds__(128) void k3b_carry()
{
    const int ch = threadIdx.x;
    float C = 0.0f;
    #pragma unroll 4
    for (int gg = 0; gg < NG; gg++) {
        g_Cg[gg * MEM + ch] = C;
        C = fmaf(g_GA[gg * MEM + ch], C, g_GB[gg * MEM + ch]);
    }
}

// ---------------------------------------------------------------------------
// Kernel 5 (FUSED v2): 512 threads, 128 frames (2 chunks) per block.
// Prologue warp-specialized: tid<256 replay scan (a,b straight from global,
// z -> Zsm); tid>=256 load W2 -> Wsm. Then 16-warp tf32 GEMM2 + epilogue.
// ---------------------------------------------------------------------------
#define BN2 128
#define WS2 132
#define ZS2 132
#define SMEM5 ((256 * WS2 + BN2 * ZS2) * 4)   // 202752 B

__global__ __launch_bounds__(512) void k5_fused(
    const float* __restrict__ W2,
    const float* __restrict__ B2,
    float* __restrict__ out)
{
    extern __shared__ float sm[];
    float* Wsm = sm;                       // [256][WS2]
    float* Zsm = sm + 256 * WS2;           // [128][ZS2]

    const int tid  = threadIdx.x;
    const int lane = tid & 31;
    const int w    = tid >> 5;
    const int wm   = w & 7;
    const int wh   = w >> 3;
    const int t0   = blockIdx.x * BN2;
    const int g    = lane >> 2;
    const int q    = lane & 3;

    if (tid < 256) {
        // Scan replay: 2 chunks x 128 channels. a,b from global (coalesced,
        // loads independent of the FMA chain -> prefetched by unroll).
        const int ch  = tid & 127;
        const int sub = tid >> 7;
        const int j   = blockIdx.x * 2 + sub;
        const int gg  = j >> 5;
        const size_t base = (size_t)(t0 + sub * 64) * MEM + ch;
        float B = fmaf(g_PA[j * MEM + ch], g_Cg[gg * MEM + ch], g_PB[j * MEM + ch]);
        #pragma unroll 8
        for (int f = 0; f < 64; f++) {
            Zsm[(sub * 64 + f) * ZS2 + ch] = tf32r(B);
            float a = __half2float(__ldg(&g_ah[base + (size_t)f * MEM]));
            float b = __half2float(__ldg(&g_bh[base + (size_t)f * MEM]));
            B = fmaf(a, B, b);
        }
    } else {
        // W2 [256][128] -> Wsm[row][k], one row per thread
        const int row = tid - 256;
        const float4* wp = (const float4*)(W2 + (size_t)row * MEM);
        #pragma unroll
        for (int i = 0; i < 32; i++) {
            float4 v = wp[i];
            Wsm[row * WS2 + i * 4 + 0] = tf32r(v.x);
            Wsm[row * WS2 + i * 4 + 1] = tf32r(v.y);
            Wsm[row * WS2 + i * 4 + 2] = tf32r(v.z);
            Wsm[row * WS2 + i * 4 + 3] = tf32r(v.w);
        }
    }
    __syncthreads();

    float cL[8][4], cR[8][4];
    #pragma unroll
    for (int nt = 0; nt < 8; nt++)
        #pragma unroll
        for (int jj = 0; jj < 4; jj++) { cL[nt][jj] = 0.f; cR[nt][jj] = 0.f; }

    #pragma unroll
    for (int k8 = 0; k8 < 16; k8++) {
        const int kk = k8 * 8;
        float aL[4], aR[4];
        {
            int ab = (wm * 16 + g) * WS2 + kk + q;
            aL[0] = Wsm[ab];
            aL[1] = Wsm[ab + 8 * WS2];
            aL[2] = Wsm[ab + 4];
            aL[3] = Wsm[ab + 8 * WS2 + 4];
            int rb = ab + 128 * WS2;
            aR[0] = Wsm[rb];
            aR[1] = Wsm[rb + 8 * WS2];
            aR[2] = Wsm[rb + 4];
            aR[3] = Wsm[rb + 8 * WS2 + 4];
        }
        #pragma unroll
        for (int nt = 0; nt < 8; nt++) {
            float b[2];
            int bb = (wh * 64 + nt * 8 + g) * ZS2 + kk + q;
            b[0] = Zsm[bb];
            b[1] = Zsm[bb + 4];
            mma8(cL[nt], aL, b);
            mma8(cR[nt], aR, b);
        }
    }

    // Epilogue: out = 1/(1+exp(v + B2)), float2 stores
    const int r0 = wm * 16 + g;
    float bL0 = B2[r0],       bL1 = B2[r0 + 8];
    float bR0 = B2[128 + r0], bR1 = B2[128 + r0 + 8];

    #pragma unroll
    for (int nt = 0; nt < 8; nt++) {
        int t = t0 + wh * 64 + nt * 8 + q * 2;
        float2 o;
        o.x = 1.0f / (1.0f + __expf(cL[nt][0] + bL0));
        o.y = 1.0f / (1.0f + __expf(cL[nt][1] + bL0));
        *(float2*)&out[(size_t)r0 * F + t] = o;
        o.x = 1.0f / (1.0f + __expf(cL[nt][2] + bL1));
        o.y = 1.0f / (1.0f + __expf(cL[nt][3] + bL1));
        *(float2*)&out[(size_t)(r0 + 8) * F + t] = o;
        o.x = 1.0f / (1.0f + __expf(cR[nt][0] + bR0));
        o.y = 1.0f / (1.0f + __expf(cR[nt][1] + bR0));
        *(float2*)&out[(size_t)(128 + r0) * F + t] = o;
        o.x = 1.0f / (1.0f + __expf(cR[nt][2] + bR1));
        o.y = 1.0f / (1.0f + __expf(cR[nt][3] + bR1));
        *(float2*)&out[(size_t)(128 + r0 + 8) * F + t] = o;
    }
}

// ---------------------------------------------------------------------------
extern "C" void kernel_launch(void* const* d_in, const int* in_sizes, int n_in,
                              void* d_out, int out_size)
{
    const float* X  = (const float*)d_in[0];  // (512, 65536)
    const float* W1 = (const float*)d_in[1];  // (256, 512)
    const float* B1 = (const float*)d_in[2];  // (256, 1)
    const float* W2 = (const float*)d_in[3];  // (256, 128)
    const float* B2 = (const float*)d_in[4];  // (256, 1)
    float* out = (float*)d_out;               // (256, 65536)

    cudaFuncSetAttribute(k1_gemm1, cudaFuncAttributeMaxDynamicSharedMemorySize, SMEM1);
    cudaFuncSetAttribute(k5_fused, cudaFuncAttributeMaxDynamicSharedMemorySize, SMEM5);

    k1_gemm1<<<F / BN1, 512, SMEM1>>>(X, W1, B1);
    k3a_prefix<<<NG, 128>>>();
    k3b_carry<<<1, 128>>>();
    k5_fused<<<F / BN2, 512, SMEM5>>>(W2, B2, out);
}

// round 7
// speedup vs baseline: 4.5058x; 1.3984x over previous
#include <cuda_runtime.h>
#include <cuda_fp16.h>
#include <math.h>
#include <stdint.h>

// Problem constants
#define F      65536
#define K1     512
#define MEM    128
#define CHUNK  64
#define NC     1024
#define NG     32
#define GS     32
#define TSCAN  65535

// Scratch
__device__ __align__(128) __half g_ah[(size_t)F * MEM];
__device__ __align__(128) __half g_bh[(size_t)F * MEM];
__device__ __align__(128) __half g_w1h[256 * K1];
__device__ __align__(128) __half g_w2h[256 * MEM];
__device__ float g_SA[NC * MEM];
__device__ float g_SB[NC * MEM];
__device__ float g_PA[NC * MEM];
__device__ float g_PB[NC * MEM];
__device__ float g_GA[NG * MEM];
__device__ float g_GB[NG * MEM];
__device__ float g_Cg[NG * MEM];

__device__ __forceinline__ float sigmoidf_(float x) {
    return 1.0f / (1.0f + __expf(-x));
}
// fp16 m16n8k16, fp32 accum
__device__ __forceinline__ void mma16(float* c, const uint32_t* a, const uint32_t* b) {
    asm("mma.sync.aligned.m16n8k16.row.col.f32.f16.f16.f32 "
        "{%0,%1,%2,%3},{%4,%5,%6,%7},{%8,%9},{%0,%1,%2,%3};"
        : "+f"(c[0]), "+f"(c[1]), "+f"(c[2]), "+f"(c[3])
        : "r"(a[0]), "r"(a[1]), "r"(a[2]), "r"(a[3]),
          "r"(b[0]), "r"(b[1]));
}
__device__ __forceinline__ void ldsm4(uint32_t* r, const __half* p) {
    uint32_t a = (uint32_t)__cvta_generic_to_shared(p);
    asm volatile("ldmatrix.sync.aligned.m8n8.x4.shared.b16 {%0,%1,%2,%3}, [%4];"
        : "=r"(r[0]), "=r"(r[1]), "=r"(r[2]), "=r"(r[3]) : "r"(a));
}
__device__ __forceinline__ void ldsm4t(uint32_t* r, const __half* p) {
    uint32_t a = (uint32_t)__cvta_generic_to_shared(p);
    asm volatile("ldmatrix.sync.aligned.m8n8.x4.trans.shared.b16 {%0,%1,%2,%3}, [%4];"
        : "=r"(r[0]), "=r"(r[1]), "=r"(r[2]), "=r"(r[3]) : "r"(a));
}
__device__ __forceinline__ void cpa16(void* dst, const void* src) {
    uint32_t d = (uint32_t)__cvta_generic_to_shared(dst);
    asm volatile("cp.async.cg.shared.global [%0], [%1], 16;" :: "r"(d), "l"(src));
}

// ---------------------------------------------------------------------------
// Kernel 0: convert W1, W2 to fp16
// ---------------------------------------------------------------------------
__global__ __launch_bounds__(256) void k0_cvt(
    const float* __restrict__ W1, const float* __restrict__ W2)
{
    int i = blockIdx.x * 256 + threadIdx.x;
    if (i < 32768) {                       // W1: 131072 floats = 32768 float4
        float4 v = ((const float4*)W1)[i];
        *(__half2*)&g_w1h[i * 4]     = __floats2half2_rn(v.x, v.y);
        *(__half2*)&g_w1h[i * 4 + 2] = __floats2half2_rn(v.z, v.w);
    } else if (i < 32768 + 8192) {         // W2: 32768 floats = 8192 float4
        int j = i - 32768;
        float4 v = ((const float4*)W2)[j];
        *(__half2*)&g_w2h[j * 4]     = __floats2half2_rn(v.x, v.y);
        *(__half2*)&g_w2h[j * 4 + 2] = __floats2half2_rn(v.z, v.w);
    }
}

// ---------------------------------------------------------------------------
// Kernel 1: fp16 tensor GEMM1 + sigmoid + a/b(fp16) + fused chunk summaries.
// 512 threads, tile M=256 x N=128, BK=64, 8 stages.
// W via cp.async (fp16, double-buffered); X via LDG->cvt->STS (sw-pipelined).
// ---------------------------------------------------------------------------
#define BN1 128
#define BK1 64
#define WS1h 72      // halves; row stride/2 = 36 == 4 mod 32 -> conflict-free
#define XS1h 136     // halves; 68 == 4 mod 32
#define WT1h (256 * WS1h)      // 18432 halves
#define XT1h (BK1 * XS1h)      // 8704 halves
#define STAGEH (WT1h + XT1h)   // 27136 halves = 54272 B
#define SSHh 136
#define SMEM1 (2 * STAGEH * 2) // 108544 B

__global__ __launch_bounds__(512) void k1_gemm1(
    const float* __restrict__ X,
    const float* __restrict__ B1)
{
    extern __shared__ __half smh[];

    const int tid  = threadIdx.x;
    const int lane = tid & 31;
    const int w    = tid >> 5;
    const int wm   = w & 7;
    const int wh   = w >> 3;
    const int t0   = blockIdx.x * BN1;
    const int g    = lane >> 2;
    const int q    = lane & 3;

    float cL[8][4], cR[8][4];
    #pragma unroll
    for (int nt = 0; nt < 8; nt++)
        #pragma unroll
        for (int j = 0; j < 4; j++) { cL[nt][j] = 0.f; cR[nt][j] = 0.f; }

    auto cpaW = [&](int s, int kb) {
        __half* Wd = smh + s * STAGEH;
        #pragma unroll
        for (int p = 0; p < 4; p++) {        // 256x64 halves = 2048 16B chunks
            int idx = tid + p * 512;
            int row = idx >> 3, c8 = (idx & 7) * 8;
            cpa16(Wd + row * WS1h + c8, g_w1h + row * K1 + kb + c8);
        }
        asm volatile("cp.async.commit_group;");
    };
    float4 xr[4];
    auto ldgX = [&](int kb) {
        #pragma unroll
        for (int p = 0; p < 4; p++) {        // 64x128 fp32 = 2048 float4
            int idx = tid + p * 512;
            int k = idx >> 5, t4 = (idx & 31) * 4;
            xr[p] = *(const float4*)(X + (size_t)(kb + k) * F + t0 + t4);
        }
    };
    auto stsX = [&](int s) {
        __half* Xd = smh + s * STAGEH + WT1h;
        #pragma unroll
        for (int p = 0; p < 4; p++) {
            int idx = tid + p * 512;
            int k = idx >> 5, t4 = (idx & 31) * 4;
            __half2 h0 = __floats2half2_rn(xr[p].x, xr[p].y);
            __half2 h1 = __floats2half2_rn(xr[p].z, xr[p].w);
            *(__half2*)&Xd[k * XS1h + t4]     = h0;
            *(__half2*)&Xd[k * XS1h + t4 + 2] = h1;
        }
    };

    // prologue: stage 0
    cpaW(0, 0);
    ldgX(0);
    stsX(0);

    for (int it = 0; it < 8; it++) {
        if (it < 7) {
            cpaW((it + 1) & 1, (it + 1) * BK1);
            ldgX((it + 1) * BK1);
            asm volatile("cp.async.wait_group 1;");
        } else {
            asm volatile("cp.async.wait_group 0;");
        }
        __syncthreads();   // W[it] + X[it] visible to all

        const __half* Wsm = smh + (it & 1) * STAGEH;
        const __half* Xsm = Wsm + WT1h;
        #pragma unroll
        for (int k16 = 0; k16 < 4; k16++) {
            const int kk = k16 * 16;
            uint32_t aL[4], aR[4];
            ldsm4(aL, Wsm + (wm * 16 + (lane & 15)) * WS1h + kk + (lane >> 4) * 8);
            ldsm4(aR, Wsm + (128 + wm * 16 + (lane & 15)) * WS1h + kk + (lane >> 4) * 8);
            #pragma unroll
            for (int nt2 = 0; nt2 < 4; nt2++) {
                uint32_t b[4];
                ldsm4t(b, Xsm + (kk + (lane & 7) + ((lane >> 3) & 1) * 8) * XS1h
                            + wh * 64 + nt2 * 16 + (lane >> 4) * 8);
                mma16(cL[nt2 * 2 + 0], aL, b + 0);
                mma16(cL[nt2 * 2 + 1], aL, b + 2);
                mma16(cR[nt2 * 2 + 0], aR, b + 0);
                mma16(cR[nt2 * 2 + 1], aR, b + 2);
            }
        }
        if (it < 7) stsX((it + 1) & 1);   // other buffer; synced at loop top
        __syncthreads();
    }

    // Epilogue: sigmoid -> a,b (fp16) into staging smem
    __half* aS = smh;                  // [128][SSHh]
    __half* bS = aS + 128 * SSHh;
    const int r0 = wm * 16 + g;
    float bl0 = B1[r0],       bl1 = B1[r0 + 8];
    float br0 = B1[128 + r0], br1 = B1[128 + r0 + 8];

    #pragma unroll
    for (int nt = 0; nt < 8; nt++) {
        #pragma unroll
        for (int j = 0; j < 4; j++) {
            int row = r0 + ((j >> 1) << 3);
            int f = wh * 64 + nt * 8 + q * 2 + (j & 1);
            float hl = sigmoidf_(cL[nt][j] + ((j >> 1) ? bl1 : bl0));
            float hr = sigmoidf_(cR[nt][j] + ((j >> 1) ? br1 : br0));
            aS[f * SSHh + row] = __float2half(hl * hr);
            bS[f * SSHh + row] = __float2half(1.0f - hl);
        }
    }
    __syncthreads();

    // Coalesced half2 global stores
    #pragma unroll
    for (int i = 0; i < 16; i++) {
        int e2 = tid + i * 512;          // 0..8191
        int f = e2 >> 6, c = e2 & 63;
        __half2 va = *(__half2*)&aS[f * SSHh + 2 * c];
        __half2 vb = *(__half2*)&bS[f * SSHh + 2 * c];
        *(__half2*)&g_ah[(size_t)(t0 + f) * MEM + 2 * c] = va;
        *(__half2*)&g_bh[(size_t)(t0 + f) * MEM + 2 * c] = vb;
    }

    // Fused chunk summaries (2 chunks of 64 frames) from the rounded values
    if (tid < 256) {
        int ch = tid & 127, hf = tid >> 7;
        int tb = t0 + hf * 64;
        float A = 1.0f, B = 0.0f;
        #pragma unroll 8
        for (int f2 = 0; f2 < 64; f2++) {
            if (tb + f2 < TSCAN) {
                int fl = hf * 64 + f2;
                float a = __half2float(aS[fl * SSHh + ch]);
                float b = __half2float(bS[fl * SSHh + ch]);
                B = fmaf(a, B, b);
                A *= a;
            }
        }
        g_SA[(blockIdx.x * 2 + hf) * MEM + ch] = A;
        g_SB[(blockIdx.x * 2 + hf) * MEM + ch] = B;
    }
}

// ---------------------------------------------------------------------------
// Kernel 3a/3b: carry hierarchy
// ---------------------------------------------------------------------------
__global__ __launch_bounds__(128) void k3a_prefix()
{
    const int ch = threadIdx.x;
    const int gg = blockIdx.x;
    float A = 1.0f, B = 0.0f;
    #pragma unroll 4
    for (int s = 0; s < GS; s++) {
        int j = gg * GS + s;
        g_PA[j * MEM + ch] = A;
        g_PB[j * MEM + ch] = B;
        float sa = g_SA[j * MEM + ch];
        float sb = g_SB[j * MEM + ch];
        B = fmaf(sa, B, sb);
        A *= sa;
    }
    g_GA[gg * MEM + ch] = A;
    g_GB[gg * MEM + ch] = B;
}

__global__ __launch_bounds__(128) void k3b_carry()
{
    const int ch = threadIdx.x;
    float C = 0.0f;
    #pragma unroll 4
    for (int gg = 0; gg < NG; gg++) {
        g_Cg[gg * MEM + ch] = C;
        C = fmaf(g_GA[gg * MEM + ch], C, g_GB[gg * MEM + ch]);
    }
}

// ---------------------------------------------------------------------------
// Kernel 5 (FUSED, fp16): 512 threads, 128 frames (2 chunks) per block.
// Prologue: tid<256 replay scan -> z (fp16) into Zsm[k=ch][n=frame];
// tid>=256 load W2 fp16 -> Wsm. Then 16-warp fp16 GEMM2 + epilogue.
// ---------------------------------------------------------------------------
#define BN2 128
#define WS5h 136
#define ZS5h 136
#define SMEM5 ((256 * WS5h + MEM * ZS5h) * 2)   // 104448 B

__global__ __launch_bounds__(512) void k5_fused(
    const float* __restrict__ B2,
    float* __restrict__ out)
{
    extern __shared__ __half smh[];
    __half* Wsm = smh;                     // [256][WS5h]
    __half* Zsm = smh + 256 * WS5h;        // [128 ch][ZS5h frames]

    const int tid  = threadIdx.x;
    const int lane = tid & 31;
    const int w    = tid >> 5;
    const int wm   = w & 7;
    const int wh   = w >> 3;
    const int t0   = blockIdx.x * BN2;
    const int g    = lane >> 2;
    const int q    = lane & 3;

    if (tid < 256) {
        // Scan replay: 2 chunks x 128 channels, fp32 state, fp16 z out.
        const int ch  = tid & 127;
        const int sub = tid >> 7;
        const int j   = blockIdx.x * 2 + sub;
        const int gg  = j >> 5;
        const size_t base = (size_t)(t0 + sub * 64) * MEM + ch;
        float B = fmaf(g_PA[j * MEM + ch], g_Cg[gg * MEM + ch], g_PB[j * MEM + ch]);
        #pragma unroll 8
        for (int f = 0; f < 64; f++) {
            Zsm[ch * ZS5h + sub * 64 + f] = __float2half(B);
            float a = __half2float(__ldg(&g_ah[base + (size_t)f * MEM]));
            float b = __half2float(__ldg(&g_bh[base + (size_t)f * MEM]));
            B = fmaf(a, B, b);
        }
    } else {
        // W2 fp16 [256][128] -> Wsm[row][k], one row per thread
        const int row = tid - 256;
        const float4* wp = (const float4*)(g_w2h + (size_t)row * MEM);
        #pragma unroll
        for (int i = 0; i < 16; i++) {      // 128 halves = 16 x 16B
            float4 v = wp[i];
            *(float4*)&Wsm[row * WS5h + i * 8] = v;
        }
    }
    __syncthreads();

    float cL[8][4], cR[8][4];
    #pragma unroll
    for (int nt = 0; nt < 8; nt++)
        #pragma unroll
        for (int jj = 0; jj < 4; jj++) { cL[nt][jj] = 0.f; cR[nt][jj] = 0.f; }

    #pragma unroll
    for (int k16 = 0; k16 < 8; k16++) {
        const int kk = k16 * 16;
        uint32_t aL[4], aR[4];
        ldsm4(aL, Wsm + (wm * 16 + (lane & 15)) * WS5h + kk + (lane >> 4) * 8);
        ldsm4(aR, Wsm + (128 + wm * 16 + (lane & 15)) * WS5h + kk + (lane >> 4) * 8);
        #pragma unroll
        for (int nt2 = 0; nt2 < 4; nt2++) {
            uint32_t b[4];
            ldsm4t(b, Zsm + (kk + (lane & 7) + ((lane >> 3) & 1) * 8) * ZS5h
                        + wh * 64 + nt2 * 16 + (lane >> 4) * 8);
            mma16(cL[nt2 * 2 + 0], aL, b + 0);
            mma16(cL[nt2 * 2 + 1], aL, b + 2);
            mma16(cR[nt2 * 2 + 0], aR, b + 0);
            mma16(cR[nt2 * 2 + 1], aR, b + 2);
        }
    }

    // Epilogue: out = 1/(1+exp(v + B2)), float2 stores
    const int r0 = wm * 16 + g;
    float bL0 = B2[r0],       bL1 = B2[r0 + 8];
    float bR0 = B2[128 + r0], bR1 = B2[128 + r0 + 8];

    #pragma unroll
    for (int nt = 0; nt < 8; nt++) {
        int t = t0 + wh * 64 + nt * 8 + q * 2;
        float2 o;
        o.x = 1.0f / (1.0f + __expf(cL[nt][0] + bL0));
        o.y = 1.0f / (1.0f + __expf(cL[nt][1] + bL0));
        *(float2*)&out[(size_t)r0 * F + t] = o;
        o.x = 1.0f / (1.0f + __expf(cL[nt][2] + bL1));
        o.y = 1.0f / (1.0f + __expf(cL[nt][3] + bL1));
        *(float2*)&out[(size_t)(r0 + 8) * F + t] = o;
        o.x = 1.0f / (1.0f + __expf(cR[nt][0] + bR0));
        o.y = 1.0f / (1.0f + __expf(cR[nt][1] + bR0));
        *(float2*)&out[(size_t)(128 + r0) * F + t] = o;
        o.x = 1.0f / (1.0f + __expf(cR[nt][2] + bR1));
        o.y = 1.0f / (1.0f + __expf(cR[nt][3] + bR1));
        *(float2*)&out[(size_t)(128 + r0 + 8) * F + t] = o;
    }
}

// ---------------------------------------------------------------------------
extern "C" void kernel_launch(void* const* d_in, const int* in_sizes, int n_in,
                              void* d_out, int out_size)
{
    const float* X  = (const float*)d_in[0];  // (512, 65536)
    const float* W1 = (const float*)d_in[1];  // (256, 512)
    const float* B1 = (const float*)d_in[2];  // (256, 1)
    const float* W2 = (const float*)d_in[3];  // (256, 128)
    const float* B2 = (const float*)d_in[4];  // (256, 1)
    float* out = (float*)d_out;               // (256, 65536)

    cudaFuncSetAttribute(k1_gemm1, cudaFuncAttributeMaxDynamicSharedMemorySize, SMEM1);
    cudaFuncSetAttribute(k5_fused, cudaFuncAttributeMaxDynamicSharedMemorySize, SMEM5);

    k0_cvt<<<160, 256>>>(W1, W2);
    k1_gemm1<<<F / BN1, 512, SMEM1>>>(X, B1);
    k3a_prefix<<<NG, 128>>>();
    k3b_carry<<<1, 128>>>();
    k5_fused<<<F / BN2, 512, SMEM5>>>(B2, out);
}

// round 11
// speedup vs baseline: 5.1739x; 1.1483x over previous
#include <cuda_runtime.h>
#include <cuda_fp16.h>
#include <math.h>
#include <stdint.h>

// Problem constants
#define F      65536
#define K1     512
#define MEM    128
#define CHUNK  64
#define NC     1024
#define NG     32
#define GS     32
#define TSCAN  65535

// Scratch
__device__ __align__(128) __half g_ah[(size_t)F * MEM];
__device__ __align__(128) __half g_bh[(size_t)F * MEM];
__device__ __align__(128) __half g_w1h[256 * K1];
__device__ __align__(128) __half g_w2h[256 * MEM];
__device__ float g_SA[NC * MEM];
__device__ float g_SB[NC * MEM];
__device__ float g_PA[NC * MEM];
__device__ float g_PB[NC * MEM];
__device__ float g_GA[NG * MEM];
__device__ float g_GB[NG * MEM];
__device__ float g_Cg[NG * MEM];

__device__ __forceinline__ float sigmoidf_(float x) {
    return 1.0f / (1.0f + __expf(-x));
}
__device__ __forceinline__ void mma16(float* c, const uint32_t* a, const uint32_t* b) {
    asm("mma.sync.aligned.m16n8k16.row.col.f32.f16.f16.f32 "
        "{%0,%1,%2,%3},{%4,%5,%6,%7},{%8,%9},{%0,%1,%2,%3};"
        : "+f"(c[0]), "+f"(c[1]), "+f"(c[2]), "+f"(c[3])
        : "r"(a[0]), "r"(a[1]), "r"(a[2]), "r"(a[3]),
          "r"(b[0]), "r"(b[1]));
}
__device__ __forceinline__ void ldsm4(uint32_t* r, const __half* p) {
    uint32_t a = (uint32_t)__cvta_generic_to_shared(p);
    asm volatile("ldmatrix.sync.aligned.m8n8.x4.shared.b16 {%0,%1,%2,%3}, [%4];"
        : "=r"(r[0]), "=r"(r[1]), "=r"(r[2]), "=r"(r[3]) : "r"(a));
}
__device__ __forceinline__ void ldsm4t(uint32_t* r, const __half* p) {
    uint32_t a = (uint32_t)__cvta_generic_to_shared(p);
    asm volatile("ldmatrix.sync.aligned.m8n8.x4.trans.shared.b16 {%0,%1,%2,%3}, [%4];"
        : "=r"(r[0]), "=r"(r[1]), "=r"(r[2]), "=r"(r[3]) : "r"(a));
}
__device__ __forceinline__ void cpa16(void* dst, const void* src) {
    uint32_t d = (uint32_t)__cvta_generic_to_shared(dst);
    asm volatile("cp.async.cg.shared.global [%0], [%1], 16;" :: "r"(d), "l"(src));
}

// ---------------------------------------------------------------------------
// Kernel 0: convert W1, W2 to fp16
// ---------------------------------------------------------------------------
__global__ __launch_bounds__(256) void k0_cvt(
    const float* __restrict__ W1, const float* __restrict__ W2)
{
    int i = blockIdx.x * 256 + threadIdx.x;
    if (i < 32768) {
        float4 v = ((const float4*)W1)[i];
        *(__half2*)&g_w1h[i * 4]     = __floats2half2_rn(v.x, v.y);
        *(__half2*)&g_w1h[i * 4 + 2] = __floats2half2_rn(v.z, v.w);
    } else if (i < 32768 + 8192) {
        int j = i - 32768;
        float4 v = ((const float4*)W2)[j];
        *(__half2*)&g_w2h[j * 4]     = __floats2half2_rn(v.x, v.y);
        *(__half2*)&g_w2h[j * 4 + 2] = __floats2half2_rn(v.z, v.w);
    }
}

// ---------------------------------------------------------------------------
// Kernel 1: fp16 tensor GEMM1 + sigmoid + a/b(fp16) + fused chunk summaries.
// 512 threads, tile M=256 x N=128, BK=64, 8 stages.
// ---------------------------------------------------------------------------
#define BN1 128
#define BK1 64
#define WS1h 72
#define XS1h 136
#define WT1h (256 * WS1h)
#define XT1h (BK1 * XS1h)
#define STAGEH (WT1h + XT1h)
#define SSHh 136
#define SMEM1 (2 * STAGEH * 2)

__global__ __launch_bounds__(512) void k1_gemm1(
    const float* __restrict__ X,
    const float* __restrict__ B1)
{
    extern __shared__ __half smh[];

    const int tid  = threadIdx.x;
    const int lane = tid & 31;
    const int w    = tid >> 5;
    const int wm   = w & 7;
    const int wh   = w >> 3;
    const int t0   = blockIdx.x * BN1;
    const int g    = lane >> 2;
    const int q    = lane & 3;

    float cL[8][4], cR[8][4];
    #pragma unroll
    for (int nt = 0; nt < 8; nt++)
        #pragma unroll
        for (int j = 0; j < 4; j++) { cL[nt][j] = 0.f; cR[nt][j] = 0.f; }

    auto cpaW = [&](int s, int kb) {
        __half* Wd = smh + s * STAGEH;
        #pragma unroll
        for (int p = 0; p < 4; p++) {
            int idx = tid + p * 512;
            int row = idx >> 3, c8 = (idx & 7) * 8;
            cpa16(Wd + row * WS1h + c8, g_w1h + row * K1 + kb + c8);
        }
        asm volatile("cp.async.commit_group;");
    };
    float4 xr[4];
    auto ldgX = [&](int kb) {
        #pragma unroll
        for (int p = 0; p < 4; p++) {
            int idx = tid + p * 512;
            int k = idx >> 5, t4 = (idx & 31) * 4;
            xr[p] = *(const float4*)(X + (size_t)(kb + k) * F + t0 + t4);
        }
    };
    auto stsX = [&](int s) {
        __half* Xd = smh + s * STAGEH + WT1h;
        #pragma unroll
        for (int p = 0; p < 4; p++) {
            int idx = tid + p * 512;
            int k = idx >> 5, t4 = (idx & 31) * 4;
            __half2 h0 = __floats2half2_rn(xr[p].x, xr[p].y);
            __half2 h1 = __floats2half2_rn(xr[p].z, xr[p].w);
            *(__half2*)&Xd[k * XS1h + t4]     = h0;
            *(__half2*)&Xd[k * XS1h + t4 + 2] = h1;
        }
    };

    cpaW(0, 0);
    ldgX(0);
    stsX(0);

    for (int it = 0; it < 8; it++) {
        if (it < 7) {
            cpaW((it + 1) & 1, (it + 1) * BK1);
            ldgX((it + 1) * BK1);
            asm volatile("cp.async.wait_group 1;");
        } else {
            asm volatile("cp.async.wait_group 0;");
        }
        __syncthreads();

        const __half* Wsm = smh + (it & 1) * STAGEH;
        const __half* Xsm = Wsm + WT1h;
        #pragma unroll
        for (int k16 = 0; k16 < 4; k16++) {
            const int kk = k16 * 16;
            uint32_t aL[4], aR[4];
            ldsm4(aL, Wsm + (wm * 16 + (lane & 15)) * WS1h + kk + (lane >> 4) * 8);
            ldsm4(aR, Wsm + (128 + wm * 16 + (lane & 15)) * WS1h + kk + (lane >> 4) * 8);
            #pragma unroll
            for (int nt2 = 0; nt2 < 4; nt2++) {
                uint32_t b[4];
                ldsm4t(b, Xsm + (kk + (lane & 7) + ((lane >> 3) & 1) * 8) * XS1h
                            + wh * 64 + nt2 * 16 + (lane >> 4) * 8);
                mma16(cL[nt2 * 2 + 0], aL, b + 0);
                mma16(cL[nt2 * 2 + 1], aL, b + 2);
                mma16(cR[nt2 * 2 + 0], aR, b + 0);
                mma16(cR[nt2 * 2 + 1], aR, b + 2);
            }
        }
        if (it < 7) stsX((it + 1) & 1);
        __syncthreads();
    }

    // Epilogue: sigmoid -> a,b (fp16) into staging smem
    __half* aS = smh;
    __half* bS = aS + 128 * SSHh;
    const int r0 = wm * 16 + g;
    float bl0 = B1[r0],       bl1 = B1[r0 + 8];
    float br0 = B1[128 + r0], br1 = B1[128 + r0 + 8];

    #pragma unroll
    for (int nt = 0; nt < 8; nt++) {
        #pragma unroll
        for (int j = 0; j < 4; j++) {
            int row = r0 + ((j >> 1) << 3);
            int f = wh * 64 + nt * 8 + q * 2 + (j & 1);
            float hl = sigmoidf_(cL[nt][j] + ((j >> 1) ? bl1 : bl0));
            float hr = sigmoidf_(cR[nt][j] + ((j >> 1) ? br1 : br0));
            aS[f * SSHh + row] = __float2half(hl * hr);
            bS[f * SSHh + row] = __float2half(1.0f - hl);
        }
    }
    __syncthreads();

    #pragma unroll
    for (int i = 0; i < 16; i++) {
        int e2 = tid + i * 512;
        int f = e2 >> 6, c = e2 & 63;
        __half2 va = *(__half2*)&aS[f * SSHh + 2 * c];
        __half2 vb = *(__half2*)&bS[f * SSHh + 2 * c];
        *(__half2*)&g_ah[(size_t)(t0 + f) * MEM + 2 * c] = va;
        *(__half2*)&g_bh[(size_t)(t0 + f) * MEM + 2 * c] = vb;
    }

    if (tid < 256) {
        int ch = tid & 127, hf = tid >> 7;
        int tb = t0 + hf * 64;
        float A = 1.0f, B = 0.0f;
        #pragma unroll 8
        for (int f2 = 0; f2 < 64; f2++) {
            if (tb + f2 < TSCAN) {
                int fl = hf * 64 + f2;
                float a = __half2float(aS[fl * SSHh + ch]);
                float b = __half2float(bS[fl * SSHh + ch]);
                B = fmaf(a, B, b);
                A *= a;
            }
        }
        g_SA[(blockIdx.x * 2 + hf) * MEM + ch] = A;
        g_SB[(blockIdx.x * 2 + hf) * MEM + ch] = B;
    }
}

// ---------------------------------------------------------------------------
// Kernel 3a: within-group exclusive prefix. Loads hoisted into registers
// (addresses independent of the chain) so latency is paid once, not 32x.
// ---------------------------------------------------------------------------
__global__ __launch_bounds__(128) void k3a_prefix()
{
    const int ch = threadIdx.x;
    const int gg = blockIdx.x;
    float sa[GS], sb[GS];
    #pragma unroll
    for (int s = 0; s < GS; s++) {
        sa[s] = g_SA[(gg * GS + s) * MEM + ch];
        sb[s] = g_SB[(gg * GS + s) * MEM + ch];
    }
    float A = 1.0f, B = 0.0f;
    #pragma unroll
    for (int s = 0; s < GS; s++) {
        g_PA[(gg * GS + s) * MEM + ch] = A;
        g_PB[(gg * GS + s) * MEM + ch] = B;
        B = fmaf(sa[s], B, sb[s]);
        A *= sa[s];
    }
    g_GA[gg * MEM + ch] = A;
    g_GB[gg * MEM + ch] = B;
}

__global__ __launch_bounds__(128) void k3b_carry()
{
    const int ch = threadIdx.x;
    float ga[NG], gb[NG];
    #pragma unroll
    for (int g2 = 0; g2 < NG; g2++) {
        ga[g2] = g_GA[g2 * MEM + ch];
        gb[g2] = g_GB[g2 * MEM + ch];
    }
    float C = 0.0f;
    #pragma unroll
    for (int g2 = 0; g2 < NG; g2++) {
        g_Cg[g2 * MEM + ch] = C;
        C = fmaf(ga[g2], C, gb[g2]);
    }
}

// ---------------------------------------------------------------------------
// Kernel 5 (FUSED, fp16): 256 threads, 64 frames (1 chunk) per block,
// grid 1024, ~88KB smem -> 2 blocks/SM (replay of one block overlaps mma of
// the other). tid<128 replay scan -> Zsm; tid>=128 load W2 -> Wsm.
// ---------------------------------------------------------------------------
#define BN2 64
#define WS5h 136
#define ZS5h 72
#define SMEM5 ((256 * WS5h + MEM * ZS5h) * 2)   // 88064 B

__global__ __launch_bounds__(256) void k5_fused(
    const float* __restrict__ B2,
    float* __restrict__ out)
{
    extern __shared__ __half smh[];
    __half* Wsm = smh;                     // [256][WS5h]
    __half* Zsm = smh + 256 * WS5h;        // [128 ch][ZS5h frames]

    const int tid  = threadIdx.x;
    const int lane = tid & 31;
    const int w    = tid >> 5;             // 0..7
    const int t0   = blockIdx.x * BN2;
    const int g    = lane >> 2;
    const int q    = lane & 3;

    if (tid < 128) {
        // Scan replay: 1 chunk x 128 channels
        const int ch = tid;
        const int j  = blockIdx.x;
        const int gg = j >> 5;
        const size_t base = (size_t)t0 * MEM + ch;
        float B = fmaf(g_PA[j * MEM + ch], g_Cg[gg * MEM + ch], g_PB[j * MEM + ch]);
        #pragma unroll 8
        for (int f = 0; f < 64; f++) {
            Zsm[ch * ZS5h + f] = __float2half(B);
            float a = __half2float(__ldg(&g_ah[base + (size_t)f * MEM]));
            float b = __half2float(__ldg(&g_bh[base + (size_t)f * MEM]));
            B = fmaf(a, B, b);
        }
    } else {
        // W2 fp16 [256][128] -> Wsm, two rows per thread
        const int r = tid - 128;
        #pragma unroll
        for (int h = 0; h < 2; h++) {
            int row = r + h * 128;
            const float4* wp = (const float4*)(g_w2h + (size_t)row * MEM);
            #pragma unroll
            for (int i = 0; i < 16; i++) {
                float4 v = wp[i];
                *(float4*)&Wsm[row * WS5h + i * 8] = v;
            }
        }
    }
    __syncthreads();

    float cL[8][4], cR[8][4];
    #pragma unroll
    for (int nt = 0; nt < 8; nt++)
        #pragma unroll
        for (int jj = 0; jj < 4; jj++) { cL[nt][jj] = 0.f; cR[nt][jj] = 0.f; }

    #pragma unroll
    for (int k16 = 0; k16 < 8; k16++) {
        const int kk = k16 * 16;
        uint32_t aL[4], aR[4];
        ldsm4(aL, Wsm + (w * 16 + (lane & 15)) * WS5h + kk + (lane >> 4) * 8);
        ldsm4(aR, Wsm + (128 + w * 16 + (lane & 15)) * WS5h + kk + (lane >> 4) * 8);
        #pragma unroll
        for (int nt2 = 0; nt2 < 4; nt2++) {
            uint32_t b[4];
            ldsm4t(b, Zsm + (kk + (lane & 7) + ((lane >> 3) & 1) * 8) * ZS5h
                        + nt2 * 16 + (lane >> 4) * 8);
            mma16(cL[nt2 * 2 + 0], aL, b + 0);
            mma16(cL[nt2 * 2 + 1], aL, b + 2);
            mma16(cR[nt2 * 2 + 0], aR, b + 0);
            mma16(cR[nt2 * 2 + 1], aR, b + 2);
        }
    }

    // Epilogue: out = 1/(1+exp(v + B2)), float2 stores
    const int r0 = w * 16 + g;
    float bL0 = B2[r0],       bL1 = B2[r0 + 8];
    float bR0 = B2[128 + r0], bR1 = B2[128 + r0 + 8];

    #pragma unroll
    for (int nt = 0; nt < 8; nt++) {
        int t = t0 + nt * 8 + q * 2;
        float2 o;
        o.x = 1.0f / (1.0f + __expf(cL[nt][0] + bL0));
        o.y = 1.0f / (1.0f + __expf(cL[nt][1] + bL0));
        *(float2*)&out[(size_t)r0 * F + t] = o;
        o.x = 1.0f / (1.0f + __expf(cL[nt][2] + bL1));
        o.y = 1.0f / (1.0f + __expf(cL[nt][3] + bL1));
        *(float2*)&out[(size_t)(r0 + 8) * F + t] = o;
        o.x = 1.0f / (1.0f + __expf(cR[nt][0] + bR0));
        o.y = 1.0f / (1.0f + __expf(cR[nt][1] + bR0));
        *(float2*)&out[(size_t)(128 + r0) * F + t] = o;
        o.x = 1.0f / (1.0f + __expf(cR[nt][2] + bR1));
        o.y = 1.0f / (1.0f + __expf(cR[nt][3] + bR1));
        *(float2*)&out[(size_t)(128 + r0 + 8) * F + t] = o;
    }
}

// ---------------------------------------------------------------------------
extern "C" void kernel_launch(void* const* d_in, const int* in_sizes, int n_in,
                              void* d_out, int out_size)
{
    const float* X  = (const float*)d_in[0];
    const float* W1 = (const float*)d_in[1];
    const float* B1 = (const float*)d_in[2];
    const float* W2 = (const float*)d_in[3];
    const float* B2 = (const float*)d_in[4];
    float* out = (float*)d_out;

    cudaFuncSetAttribute(k1_gemm1, cudaFuncAttributeMaxDynamicSharedMemorySize, SMEM1);
    cudaFuncSetAttribute(k5_fused, cudaFuncAttributeMaxDynamicSharedMemorySize, SMEM5);

    k0_cvt<<<160, 256>>>(W1, W2);
    k1_gemm1<<<F / BN1, 512, SMEM1>>>(X, B1);
    k3a_prefix<<<NG, 128>>>();
    k3b_carry<<<1, 128>>>();
    k5_fused<<<NC, 256, SMEM5>>>(B2, out);
}

// round 12
// speedup vs baseline: 5.5989x; 1.0821x over previous
#include <cuda_runtime.h>
#include <cuda_fp16.h>
#include <math.h>
#include <stdint.h>

// Problem constants
#define F      65536
#define K1     512
#define MEM    128
#define CHUNK  32
#define NC     2048      // F/CHUNK
#define NG     64        // carry groups
#define GS     32        // chunks per group
#define TSCAN  65535

// Scratch
__device__ __align__(128) __half g_ah[(size_t)F * MEM];
__device__ __align__(128) __half g_bh[(size_t)F * MEM];
__device__ __align__(128) __half g_w1h[256 * K1];
__device__ __align__(128) __half g_w2h[256 * MEM];
__device__ float g_SA[NC * MEM];
__device__ float g_SB[NC * MEM];
__device__ float g_PA[NC * MEM];
__device__ float g_PB[NC * MEM];
__device__ float g_GA[NG * MEM];
__device__ float g_GB[NG * MEM];
__device__ float g_Cg[NG * MEM];

__device__ __forceinline__ float sigmoidf_(float x) {
    return 1.0f / (1.0f + __expf(-x));
}
__device__ __forceinline__ void mma16(float* c, const uint32_t* a, const uint32_t* b) {
    asm("mma.sync.aligned.m16n8k16.row.col.f32.f16.f16.f32 "
        "{%0,%1,%2,%3},{%4,%5,%6,%7},{%8,%9},{%0,%1,%2,%3};"
        : "+f"(c[0]), "+f"(c[1]), "+f"(c[2]), "+f"(c[3])
        : "r"(a[0]), "r"(a[1]), "r"(a[2]), "r"(a[3]),
          "r"(b[0]), "r"(b[1]));
}
__device__ __forceinline__ void ldsm4(uint32_t* r, const __half* p) {
    uint32_t a = (uint32_t)__cvta_generic_to_shared(p);
    asm volatile("ldmatrix.sync.aligned.m8n8.x4.shared.b16 {%0,%1,%2,%3}, [%4];"
        : "=r"(r[0]), "=r"(r[1]), "=r"(r[2]), "=r"(r[3]) : "r"(a));
}
__device__ __forceinline__ void ldsm4t(uint32_t* r, const __half* p) {
    uint32_t a = (uint32_t)__cvta_generic_to_shared(p);
    asm volatile("ldmatrix.sync.aligned.m8n8.x4.trans.shared.b16 {%0,%1,%2,%3}, [%4];"
        : "=r"(r[0]), "=r"(r[1]), "=r"(r[2]), "=r"(r[3]) : "r"(a));
}
__device__ __forceinline__ void cpa16(void* dst, const void* src) {
    uint32_t d = (uint32_t)__cvta_generic_to_shared(dst);
    asm volatile("cp.async.cg.shared.global [%0], [%1], 16;" :: "r"(d), "l"(src));
}

// ---------------------------------------------------------------------------
// Kernel 0: convert W1, W2 to fp16
// ---------------------------------------------------------------------------
__global__ __launch_bounds__(256) void k0_cvt(
    const float* __restrict__ W1, const float* __restrict__ W2)
{
    int i = blockIdx.x * 256 + threadIdx.x;
    if (i < 32768) {
        float4 v = ((const float4*)W1)[i];
        *(__half2*)&g_w1h[i * 4]     = __floats2half2_rn(v.x, v.y);
        *(__half2*)&g_w1h[i * 4 + 2] = __floats2half2_rn(v.z, v.w);
    } else if (i < 32768 + 8192) {
        int j = i - 32768;
        float4 v = ((const float4*)W2)[j];
        *(__half2*)&g_w2h[j * 4]     = __floats2half2_rn(v.x, v.y);
        *(__half2*)&g_w2h[j * 4 + 2] = __floats2half2_rn(v.z, v.w);
    }
}

// ---------------------------------------------------------------------------
// Kernel 1: fp16 tensor GEMM1 + sigmoid + a/b(fp16) + fused chunk summaries.
// 512 threads, tile M=256 x N=128, BK=64, 8 stages, ONE sync per stage.
// ---------------------------------------------------------------------------
#define BN1 128
#define BK1 64
#define WS1h 72
#define XS1h 136
#define WT1h (256 * WS1h)
#define XT1h (BK1 * XS1h)
#define STAGEH (WT1h + XT1h)
#define SSHh 136
#define SMEM1 (2 * STAGEH * 2)

__global__ __launch_bounds__(512) void k1_gemm1(
    const float* __restrict__ X,
    const float* __restrict__ B1)
{
    extern __shared__ __half smh[];

    const int tid  = threadIdx.x;
    const int lane = tid & 31;
    const int w    = tid >> 5;
    const int wm   = w & 7;
    const int wh   = w >> 3;
    const int t0   = blockIdx.x * BN1;
    const int g    = lane >> 2;
    const int q    = lane & 3;

    float cL[8][4], cR[8][4];
    #pragma unroll
    for (int nt = 0; nt < 8; nt++)
        #pragma unroll
        for (int j = 0; j < 4; j++) { cL[nt][j] = 0.f; cR[nt][j] = 0.f; }

    auto cpaW = [&](int s, int kb) {
        __half* Wd = smh + s * STAGEH;
        #pragma unroll
        for (int p = 0; p < 4; p++) {
            int idx = tid + p * 512;
            int row = idx >> 3, c8 = (idx & 7) * 8;
            cpa16(Wd + row * WS1h + c8, g_w1h + row * K1 + kb + c8);
        }
        asm volatile("cp.async.commit_group;");
    };
    float4 xr[4];
    auto ldgX = [&](int kb) {
        #pragma unroll
        for (int p = 0; p < 4; p++) {
            int idx = tid + p * 512;
            int k = idx >> 5, t4 = (idx & 31) * 4;
            xr[p] = *(const float4*)(X + (size_t)(kb + k) * F + t0 + t4);
        }
    };
    auto stsX = [&](int s) {
        __half* Xd = smh + s * STAGEH + WT1h;
        #pragma unroll
        for (int p = 0; p < 4; p++) {
            int idx = tid + p * 512;
            int k = idx >> 5, t4 = (idx & 31) * 4;
            __half2 h0 = __floats2half2_rn(xr[p].x, xr[p].y);
            __half2 h1 = __floats2half2_rn(xr[p].z, xr[p].w);
            *(__half2*)&Xd[k * XS1h + t4]     = h0;
            *(__half2*)&Xd[k * XS1h + t4 + 2] = h1;
        }
    };

    cpaW(0, 0);
    ldgX(0);
    stsX(0);

    for (int it = 0; it < 8; it++) {
        asm volatile("cp.async.wait_group 0;");
        __syncthreads();   // W[it]+X[it] visible; all buf[it+1] readers done

        if (it < 7) {
            cpaW((it + 1) & 1, (it + 1) * BK1);
            ldgX((it + 1) * BK1);
        }

        const __half* Wsm = smh + (it & 1) * STAGEH;
        const __half* Xsm = Wsm + WT1h;
        #pragma unroll
        for (int k16 = 0; k16 < 4; k16++) {
            const int kk = k16 * 16;
            uint32_t aL[4], aR[4];
            ldsm4(aL, Wsm + (wm * 16 + (lane & 15)) * WS1h + kk + (lane >> 4) * 8);
            ldsm4(aR, Wsm + (128 + wm * 16 + (lane & 15)) * WS1h + kk + (lane >> 4) * 8);
            #pragma unroll
            for (int nt2 = 0; nt2 < 4; nt2++) {
                uint32_t b[4];
                ldsm4t(b, Xsm + (kk + (lane & 7) + ((lane >> 3) & 1) * 8) * XS1h
                            + wh * 64 + nt2 * 16 + (lane >> 4) * 8);
                mma16(cL[nt2 * 2 + 0], aL, b + 0);
                mma16(cL[nt2 * 2 + 1], aL, b + 2);
                mma16(cR[nt2 * 2 + 0], aR, b + 0);
                mma16(cR[nt2 * 2 + 1], aR, b + 2);
            }
        }
        if (it < 7) stsX((it + 1) & 1);
    }
    __syncthreads();

    // Epilogue: sigmoid -> a,b (fp16) into staging smem
    __half* aS = smh;
    __half* bS = aS + 128 * SSHh;
    const int r0 = wm * 16 + g;
    float bl0 = B1[r0],       bl1 = B1[r0 + 8];
    float br0 = B1[128 + r0], br1 = B1[128 + r0 + 8];

    #pragma unroll
    for (int nt = 0; nt < 8; nt++) {
        #pragma unroll
        for (int j = 0; j < 4; j++) {
            int row = r0 + ((j >> 1) << 3);
            int f = wh * 64 + nt * 8 + q * 2 + (j & 1);
            float hl = sigmoidf_(cL[nt][j] + ((j >> 1) ? bl1 : bl0));
            float hr = sigmoidf_(cR[nt][j] + ((j >> 1) ? br1 : br0));
            aS[f * SSHh + row] = __float2half(hl * hr);
            bS[f * SSHh + row] = __float2half(1.0f - hl);
        }
    }
    __syncthreads();

    #pragma unroll
    for (int i = 0; i < 16; i++) {
        int e2 = tid + i * 512;
        int f = e2 >> 6, c = e2 & 63;
        __half2 va = *(__half2*)&aS[f * SSHh + 2 * c];
        __half2 vb = *(__half2*)&bS[f * SSHh + 2 * c];
        *(__half2*)&g_ah[(size_t)(t0 + f) * MEM + 2 * c] = va;
        *(__half2*)&g_bh[(size_t)(t0 + f) * MEM + 2 * c] = vb;
    }

    // Fused chunk summaries: 4 chunks of 32 frames, all 512 threads active
    {
        int ch = tid & 127, qt = tid >> 7;   // quarter 0..3
        int tb = t0 + qt * CHUNK;
        float A = 1.0f, B = 0.0f;
        #pragma unroll 8
        for (int f2 = 0; f2 < CHUNK; f2++) {
            if (tb + f2 < TSCAN) {
                int fl = qt * CHUNK + f2;
                float a = __half2float(aS[fl * SSHh + ch]);
                float b = __half2float(bS[fl * SSHh + ch]);
                B = fmaf(a, B, b);
                A *= a;
            }
        }
        g_SA[(blockIdx.x * 4 + qt) * MEM + ch] = A;
        g_SB[(blockIdx.x * 4 + qt) * MEM + ch] = B;
    }
}

// ---------------------------------------------------------------------------
// Kernel 3a: within-group exclusive prefix (loads hoisted to registers).
// ---------------------------------------------------------------------------
__global__ __launch_bounds__(128) void k3a_prefix()
{
    const int ch = threadIdx.x;
    const int gg = blockIdx.x;
    float sa[GS], sb[GS];
    #pragma unroll
    for (int s = 0; s < GS; s++) {
        sa[s] = g_SA[(gg * GS + s) * MEM + ch];
        sb[s] = g_SB[(gg * GS + s) * MEM + ch];
    }
    float A = 1.0f, B = 0.0f;
    #pragma unroll
    for (int s = 0; s < GS; s++) {
        g_PA[(gg * GS + s) * MEM + ch] = A;
        g_PB[(gg * GS + s) * MEM + ch] = B;
        B = fmaf(sa[s], B, sb[s]);
        A *= sa[s];
    }
    g_GA[gg * MEM + ch] = A;
    g_GB[gg * MEM + ch] = B;
}

__global__ __launch_bounds__(128) void k3b_carry()
{
    const int ch = threadIdx.x;
    float ga[NG], gb[NG];
    #pragma unroll
    for (int g2 = 0; g2 < NG; g2++) {
        ga[g2] = g_GA[g2 * MEM + ch];
        gb[g2] = g_GB[g2 * MEM + ch];
    }
    float C = 0.0f;
    #pragma unroll
    for (int g2 = 0; g2 < NG; g2++) {
        g_Cg[g2 * MEM + ch] = C;
        C = fmaf(ga[g2], C, gb[g2]);
    }
}

// ---------------------------------------------------------------------------
// Kernel 5 (FUSED, fp16): 256 threads, 64 frames (2 chunks of 32) per block.
// W2 via cp.async (all threads, async under replay); ALL 256 threads replay
// 32-step sub-chunks in parallel. Then 8-warp fp16 GEMM2 + epilogue.
// ---------------------------------------------------------------------------
#define BN2 64
#define WS5h 136
#define ZS5h 72
#define SMEM5 ((256 * WS5h + MEM * ZS5h) * 2)   // 88064 B -> 2 blocks/SM

__global__ __launch_bounds__(256) void k5_fused(
    const float* __restrict__ B2,
    float* __restrict__ out)
{
    extern __shared__ __half smh[];
    __half* Wsm = smh;                     // [256][WS5h]
    __half* Zsm = smh + 256 * WS5h;        // [128 ch][ZS5h frames]

    const int tid  = threadIdx.x;
    const int lane = tid & 31;
    const int w    = tid >> 5;             // 0..7
    const int t0   = blockIdx.x * BN2;
    const int g    = lane >> 2;
    const int q    = lane & 3;

    // W2 -> Wsm via cp.async: 256x128 halves = 4096 16B chunks, 16 per thread
    #pragma unroll
    for (int i = 0; i < 16; i++) {
        int idx = tid + i * 256;
        int row = idx >> 4, c8 = (idx & 15) * 8;
        cpa16(Wsm + row * WS5h + c8, g_w2h + row * MEM + c8);
    }
    asm volatile("cp.async.commit_group;");

    // Scan replay: 2 sub-chunks x 128 channels, all threads, 32-step chains
    {
        const int ch  = tid & 127;
        const int sub = tid >> 7;
        const int j   = blockIdx.x * 2 + sub;
        const int gg  = j >> 5;
        const int f0  = sub * CHUNK;
        const size_t base = (size_t)(t0 + f0) * MEM + ch;
        float B = fmaf(g_PA[j * MEM + ch], g_Cg[gg * MEM + ch], g_PB[j * MEM + ch]);
        #pragma unroll 8
        for (int f = 0; f < CHUNK; f++) {
            Zsm[ch * ZS5h + f0 + f] = __float2half(B);
            float a = __half2float(__ldg(&g_ah[base + (size_t)f * MEM]));
            float b = __half2float(__ldg(&g_bh[base + (size_t)f * MEM]));
            B = fmaf(a, B, b);
        }
    }
    asm volatile("cp.async.wait_group 0;");
    __syncthreads();

    float cL[8][4], cR[8][4];
    #pragma unroll
    for (int nt = 0; nt < 8; nt++)
        #pragma unroll
        for (int jj = 0; jj < 4; jj++) { cL[nt][jj] = 0.f; cR[nt][jj] = 0.f; }

    #pragma unroll
    for (int k16 = 0; k16 < 8; k16++) {
        const int kk = k16 * 16;
        uint32_t aL[4], aR[4];
        ldsm4(aL, Wsm + (w * 16 + (lane & 15)) * WS5h + kk + (lane >> 4) * 8);
        ldsm4(aR, Wsm + (128 + w * 16 + (lane & 15)) * WS5h + kk + (lane >> 4) * 8);
        #pragma unroll
        for (int nt2 = 0; nt2 < 4; nt2++) {
            uint32_t b[4];
            ldsm4t(b, Zsm + (kk + (lane & 7) + ((lane >> 3) & 1) * 8) * ZS5h
                        + nt2 * 16 + (lane >> 4) * 8);
            mma16(cL[nt2 * 2 + 0], aL, b + 0);
            mma16(cL[nt2 * 2 + 1], aL, b + 2);
            mma16(cR[nt2 * 2 + 0], aR, b + 0);
            mma16(cR[nt2 * 2 + 1], aR, b + 2);
        }
    }

    // Epilogue: out = 1/(1+exp(v + B2)), float2 stores
    const int r0 = w * 16 + g;
    float bL0 = B2[r0],       bL1 = B2[r0 + 8];
    float bR0 = B2[128 + r0], bR1 = B2[128 + r0 + 8];

    #pragma unroll
    for (int nt = 0; nt < 8; nt++) {
        int t = t0 + nt * 8 + q * 2;
        float2 o;
        o.x = 1.0f / (1.0f + __expf(cL[nt][0] + bL0));
        o.y = 1.0f / (1.0f + __expf(cL[nt][1] + bL0));
        *(float2*)&out[(size_t)r0 * F + t] = o;
        o.x = 1.0f / (1.0f + __expf(cL[nt][2] + bL1));
        o.y = 1.0f / (1.0f + __expf(cL[nt][3] + bL1));
        *(float2*)&out[(size_t)(r0 + 8) * F + t] = o;
        o.x = 1.0f / (1.0f + __expf(cR[nt][0] + bR0));
        o.y = 1.0f / (1.0f + __expf(cR[nt][1] + bR0));
        *(float2*)&out[(size_t)(128 + r0) * F + t] = o;
        o.x = 1.0f / (1.0f + __expf(cR[nt][2] + bR1));
        o.y = 1.0f / (1.0f + __expf(cR[nt][3] + bR1));
        *(float2*)&out[(size_t)(128 + r0 + 8) * F + t] = o;
    }
}

// ---------------------------------------------------------------------------
extern "C" void kernel_launch(void* const* d_in, const int* in_sizes, int n_in,
                              void* d_out, int out_size)
{
    const float* X  = (const float*)d_in[0];
    const float* W1 = (const float*)d_in[1];
    const float* B1 = (const float*)d_in[2];
    const float* W2 = (const float*)d_in[3];
    const float* B2 = (const float*)d_in[4];
    float* out = (float*)d_out;

    cudaFuncSetAttribute(k1_gemm1, cudaFuncAttributeMaxDynamicSharedMemorySize, SMEM1);
    cudaFuncSetAttribute(k5_fused, cudaFuncAttributeMaxDynamicSharedMemorySize, SMEM5);

    k0_cvt<<<160, 256>>>(W1, W2);
    k1_gemm1<<<F / BN1, 512, SMEM1>>>(X, B1);
    k3a_prefix<<<NG, 128>>>();
    k3b_carry<<<1, 128>>>();
    k5_fused<<<NC / 2, 256, SMEM5>>>(B2, out);
}

// round 17
// speedup vs baseline: 6.1789x; 1.1036x over previous
#include <cuda_runtime.h>
#include <cuda_fp16.h>
#include <math.h>
#include <stdint.h>

// Problem constants
#define F      65536
#define K1     512
#define MEM    128
#define CHUNK  32
#define NC     2048      // F/CHUNK
#define NG     64        // carry groups
#define GS     32        // chunks per group
#define TSCAN  65535

// Scratch
// g_pq[t*128+ch] = (P_t, Q_t): intra-chunk prefix product / prefix scan
__device__ __align__(128) __half2 g_pq[(size_t)F * MEM];
__device__ __align__(128) __half g_w1h[256 * K1];
__device__ __align__(128) __half g_w2h[256 * MEM];
__device__ float g_SA[NC * MEM];
__device__ float g_SB[NC * MEM];
__device__ float g_PA[NC * MEM];
__device__ float g_PB[NC * MEM];
__device__ float g_GA[NG * MEM];
__device__ float g_GB[NG * MEM];
__device__ float g_Cg[NG * MEM];

__device__ __forceinline__ float sigmoidf_(float x) {
    return 1.0f / (1.0f + __expf(-x));
}
__device__ __forceinline__ void mma16(float* c, const uint32_t* a, const uint32_t* b) {
    asm("mma.sync.aligned.m16n8k16.row.col.f32.f16.f16.f32 "
        "{%0,%1,%2,%3},{%4,%5,%6,%7},{%8,%9},{%0,%1,%2,%3};"
        : "+f"(c[0]), "+f"(c[1]), "+f"(c[2]), "+f"(c[3])
        : "r"(a[0]), "r"(a[1]), "r"(a[2]), "r"(a[3]),
          "r"(b[0]), "r"(b[1]));
}
__device__ __forceinline__ void ldsm4(uint32_t* r, const __half* p) {
    uint32_t a = (uint32_t)__cvta_generic_to_shared(p);
    asm volatile("ldmatrix.sync.aligned.m8n8.x4.shared.b16 {%0,%1,%2,%3}, [%4];"
        : "=r"(r[0]), "=r"(r[1]), "=r"(r[2]), "=r"(r[3]) : "r"(a));
}
__device__ __forceinline__ void ldsm4t(uint32_t* r, const __half* p) {
    uint32_t a = (uint32_t)__cvta_generic_to_shared(p);
    asm volatile("ldmatrix.sync.aligned.m8n8.x4.trans.shared.b16 {%0,%1,%2,%3}, [%4];"
        : "=r"(r[0]), "=r"(r[1]), "=r"(r[2]), "=r"(r[3]) : "r"(a));
}
__device__ __forceinline__ void cpa16(void* dst, const void* src) {
    uint32_t d = (uint32_t)__cvta_generic_to_shared(dst);
    asm volatile("cp.async.cg.shared.global [%0], [%1], 16;" :: "r"(d), "l"(src));
}

// ---------------------------------------------------------------------------
// Kernel 0: convert W1, W2 to fp16
// ---------------------------------------------------------------------------
__global__ __launch_bounds__(256) void k0_cvt(
    const float* __restrict__ W1, const float* __restrict__ W2)
{
    int i = blockIdx.x * 256 + threadIdx.x;
    if (i < 32768) {
        float4 v = ((const float4*)W1)[i];
        *(__half2*)&g_w1h[i * 4]     = __floats2half2_rn(v.x, v.y);
        *(__half2*)&g_w1h[i * 4 + 2] = __floats2half2_rn(v.z, v.w);
    } else if (i < 32768 + 8192) {
        int j = i - 32768;
        float4 v = ((const float4*)W2)[j];
        *(__half2*)&g_w2h[j * 4]     = __floats2half2_rn(v.x, v.y);
        *(__half2*)&g_w2h[j * 4 + 2] = __floats2half2_rn(v.z, v.w);
    }
}

// ---------------------------------------------------------------------------
// Kernel 1: fp16 tensor GEMM1 + sigmoid + per-frame (P,Q) prefix emission
// + chunk summaries. 512 threads, tile M=256 x N=128, BK=64, 8 stages.
// ---------------------------------------------------------------------------
#define BN1 128
#define BK1 64
#define WS1h 72
#define XS1h 136
#define WT1h (256 * WS1h)
#define XT1h (BK1 * XS1h)
#define STAGEH (WT1h + XT1h)
#define SSHh 136
#define SMEM1 (2 * STAGEH * 2)

__global__ __launch_bounds__(512) void k1_gemm1(
    const float* __restrict__ X,
    const float* __restrict__ B1)
{
    extern __shared__ __half smh[];

    const int tid  = threadIdx.x;
    const int lane = tid & 31;
    const int w    = tid >> 5;
    const int wm   = w & 7;
    const int wh   = w >> 3;
    const int t0   = blockIdx.x * BN1;
    const int g    = lane >> 2;
    const int q    = lane & 3;

    float cL[8][4], cR[8][4];
    #pragma unroll
    for (int nt = 0; nt < 8; nt++)
        #pragma unroll
        for (int j = 0; j < 4; j++) { cL[nt][j] = 0.f; cR[nt][j] = 0.f; }

    auto cpaW = [&](int s, int kb) {
        __half* Wd = smh + s * STAGEH;
        #pragma unroll
        for (int p = 0; p < 4; p++) {
            int idx = tid + p * 512;
            int row = idx >> 3, c8 = (idx & 7) * 8;
            cpa16(Wd + row * WS1h + c8, g_w1h + row * K1 + kb + c8);
        }
        asm volatile("cp.async.commit_group;");
    };
    float4 xr[4];
    auto ldgX = [&](int kb) {
        #pragma unroll
        for (int p = 0; p < 4; p++) {
            int idx = tid + p * 512;
            int k = idx >> 5, t4 = (idx & 31) * 4;
            xr[p] = *(const float4*)(X + (size_t)(kb + k) * F + t0 + t4);
        }
    };
    auto stsX = [&](int s) {
        __half* Xd = smh + s * STAGEH + WT1h;
        #pragma unroll
        for (int p = 0; p < 4; p++) {
            int idx = tid + p * 512;
            int k = idx >> 5, t4 = (idx & 31) * 4;
            __half2 h0 = __floats2half2_rn(xr[p].x, xr[p].y);
            __half2 h1 = __floats2half2_rn(xr[p].z, xr[p].w);
            *(__half2*)&Xd[k * XS1h + t4]     = h0;
            *(__half2*)&Xd[k * XS1h + t4 + 2] = h1;
        }
    };

    cpaW(0, 0);
    ldgX(0);
    stsX(0);

    for (int it = 0; it < 8; it++) {
        asm volatile("cp.async.wait_group 0;");
        __syncthreads();

        if (it < 7) {
            cpaW((it + 1) & 1, (it + 1) * BK1);
            ldgX((it + 1) * BK1);
        }

        const __half* Wsm = smh + (it & 1) * STAGEH;
        const __half* Xsm = Wsm + WT1h;
        #pragma unroll
        for (int k16 = 0; k16 < 4; k16++) {
            const int kk = k16 * 16;
            uint32_t aL[4], aR[4];
            ldsm4(aL, Wsm + (wm * 16 + (lane & 15)) * WS1h + kk + (lane >> 4) * 8);
            ldsm4(aR, Wsm + (128 + wm * 16 + (lane & 15)) * WS1h + kk + (lane >> 4) * 8);
            #pragma unroll
            for (int nt2 = 0; nt2 < 4; nt2++) {
                uint32_t b[4];
                ldsm4t(b, Xsm + (kk + (lane & 7) + ((lane >> 3) & 1) * 8) * XS1h
                            + wh * 64 + nt2 * 16 + (lane >> 4) * 8);
                mma16(cL[nt2 * 2 + 0], aL, b + 0);
                mma16(cL[nt2 * 2 + 1], aL, b + 2);
                mma16(cR[nt2 * 2 + 0], aR, b + 0);
                mma16(cR[nt2 * 2 + 1], aR, b + 2);
            }
        }
        if (it < 7) stsX((it + 1) & 1);
    }
    __syncthreads();

    // Epilogue stage 1: sigmoid -> a,b (fp16) into staging smem [frame][ch]
    __half* aS = smh;
    __half* bS = aS + 128 * SSHh;
    const int r0 = wm * 16 + g;
    float bl0 = B1[r0],       bl1 = B1[r0 + 8];
    float br0 = B1[128 + r0], br1 = B1[128 + r0 + 8];

    #pragma unroll
    for (int nt = 0; nt < 8; nt++) {
        #pragma unroll
        for (int j = 0; j < 4; j++) {
            int row = r0 + ((j >> 1) << 3);
            int f = wh * 64 + nt * 8 + q * 2 + (j & 1);
            float hl = sigmoidf_(cL[nt][j] + ((j >> 1) ? bl1 : bl0));
            float hr = sigmoidf_(cR[nt][j] + ((j >> 1) ? br1 : br0));
            aS[f * SSHh + row] = __float2half(hl * hr);
            bS[f * SSHh + row] = __float2half(1.0f - hl);
        }
    }
    __syncthreads();

    // Epilogue stage 2: per-chunk prefix walk; emit (P,Q) per frame (packed
    // half2, coalesced STG) and the chunk summary. 4 chunks x 128 channels.
    {
        int ch = tid & 127, qt = tid >> 7;
        int tb = t0 + qt * CHUNK;
        float A = 1.0f, B = 0.0f;
        #pragma unroll 8
        for (int f2 = 0; f2 < CHUNK; f2++) {
            if (tb + f2 < TSCAN) {
                int fl = qt * CHUNK + f2;
                float a = __half2float(aS[fl * SSHh + ch]);
                float b = __half2float(bS[fl * SSHh + ch]);
                B = fmaf(a, B, b);
                A *= a;
            }
            g_pq[(size_t)(tb + f2) * MEM + ch] = __floats2half2_rn(A, B);
        }
        g_SA[(blockIdx.x * 4 + qt) * MEM + ch] = A;
        g_SB[(blockIdx.x * 4 + qt) * MEM + ch] = B;
    }
}

// ---------------------------------------------------------------------------
// Kernel 3a: within-group exclusive prefix (loads hoisted to registers).
// ---------------------------------------------------------------------------
__global__ __launch_bounds__(128) void k3a_prefix()
{
    const int ch = threadIdx.x;
    const int gg = blockIdx.x;
    float sa[GS], sb[GS];
    #pragma unroll
    for (int s = 0; s < GS; s++) {
        sa[s] = g_SA[(gg * GS + s) * MEM + ch];
        sb[s] = g_SB[(gg * GS + s) * MEM + ch];
    }
    float A = 1.0f, B = 0.0f;
    #pragma unroll
    for (int s = 0; s < GS; s++) {
        g_PA[(gg * GS + s) * MEM + ch] = A;
        g_PB[(gg * GS + s) * MEM + ch] = B;
        B = fmaf(sa[s], B, sb[s]);
        A *= sa[s];
    }
    g_GA[gg * MEM + ch] = A;
    g_GB[gg * MEM + ch] = B;
}

// ---------------------------------------------------------------------------
// Kernel 3b: 2-phase scan over 64 group summaries. 256 threads: each half
// handles 32 groups; chain length 32 instead of 64.
// ---------------------------------------------------------------------------
__global__ __launch_bounds__(256) void k3b_carry()
{
    __shared__ float sB[128];
    const int ch = threadIdx.x & 127;
    const int h  = threadIdx.x >> 7;
    float ga[32], gb[32];
    #pragma unroll
    for (int s = 0; s < 32; s++) {
        ga[s] = g_GA[(h * 32 + s) * MEM + ch];
        gb[s] = g_GB[(h * 32 + s) * MEM + ch];
    }
    // Phase 1: lower half computes its composed B (carry into group 32)
    if (h == 0) {
        float B = 0.0f;
        #pragma unroll
        for (int s = 0; s < 32; s++) B = fmaf(ga[s], B, gb[s]);
        sB[ch] = B;
    }
    __syncthreads();
    // Phase 2: emit carries
    float C = (h == 0) ? 0.0f : sB[ch];
    #pragma unroll
    for (int s = 0; s < 32; s++) {
        g_Cg[(h * 32 + s) * MEM + ch] = C;
        C = fmaf(ga[s], C, gb[s]);
    }
}

// ---------------------------------------------------------------------------
// Kernel 5 (FUSED, fp16): 256 threads, 64 frames (2 chunks of 32) per block.
// W2 via cp.async; z built by PARALLEL fixup z_s = P_s*C + Q_s (no serial
// chain). Then 8-warp fp16 GEMM2 + epilogue.
// ---------------------------------------------------------------------------
#define BN2 64
#define WS5h 136
#define ZS5h 72
#define SMEM5 ((256 * WS5h + MEM * ZS5h) * 2)   // 88064 B -> 2 blocks/SM

__global__ __launch_bounds__(256) void k5_fused(
    const float* __restrict__ B2,
    float* __restrict__ out)
{
    extern __shared__ __half smh[];
    __half* Wsm = smh;                     // [256][WS5h]
    __half* Zsm = smh + 256 * WS5h;        // [128 ch][ZS5h frames]

    const int tid  = threadIdx.x;
    const int lane = tid & 31;
    const int w    = tid >> 5;
    const int t0   = blockIdx.x * BN2;
    const int g    = lane >> 2;
    const int q    = lane & 3;

    // W2 -> Wsm via cp.async (async under the z fixup)
    #pragma unroll
    for (int i = 0; i < 16; i++) {
        int idx = tid + i * 256;
        int row = idx >> 4, c8 = (idx & 15) * 8;
        cpa16(Wsm + row * WS5h + c8, g_w2h + row * MEM + c8);
    }
    asm volatile("cp.async.commit_group;");

    // Parallel z fixup: z[f] = bb_{t0+f-1}. For f == sub*32 this is exactly
    // the carry into chunk jc; for f = sub*32+i (i>=1) it is P*C+Q at
    // s = t0+sub*32+i-1. All loads independent -> full MLP.
    {
        const int ch  = tid & 127;
        const int sub = tid >> 7;
        const int jc  = blockIdx.x * 2 + sub;
        const int gg  = jc >> 5;
        const int f0  = sub * CHUNK;
        float C = fmaf(g_PA[jc * MEM + ch], g_Cg[gg * MEM + ch],
                       g_PB[jc * MEM + ch]);
        Zsm[ch * ZS5h + f0] = __float2half(C);
        const __half2* pq = g_pq + (size_t)(t0 + f0) * MEM + ch;
        #pragma unroll
        for (int i = 1; i < CHUNK; i++) {
            __half2 v = pq[(size_t)(i - 1) * MEM];
            float P = __low2float(v), Q = __high2float(v);
            Zsm[ch * ZS5h + f0 + i] = __float2half(fmaf(P, C, Q));
        }
    }
    asm volatile("cp.async.wait_group 0;");
    __syncthreads();

    float cL[8][4], cR[8][4];
    #pragma unroll
    for (int nt = 0; nt < 8; nt++)
        #pragma unroll
        for (int jj = 0; jj < 4; jj++) { cL[nt][jj] = 0.f; cR[nt][jj] = 0.f; }

    #pragma unroll
    for (int k16 = 0; k16 < 8; k16++) {
        const int kk = k16 * 16;
        uint32_t aL[4], aR[4];
        ldsm4(aL, Wsm + (w * 16 + (lane & 15)) * WS5h + kk + (lane >> 4) * 8);
        ldsm4(aR, Wsm + (128 + w * 16 + (lane & 15)) * WS5h + kk + (lane >> 4) * 8);
        #pragma unroll
        for (int nt2 = 0; nt2 < 4; nt2++) {
            uint32_t b[4];
            ldsm4t(b, Zsm + (kk + (lane & 7) + ((lane >> 3) & 1) * 8) * ZS5h
                        + nt2 * 16 + (lane >> 4) * 8);
            mma16(cL[nt2 * 2 + 0], aL, b + 0);
            mma16(cL[nt2 * 2 + 1], aL, b + 2);
            mma16(cR[nt2 * 2 + 0], aR, b + 0);
            mma16(cR[nt2 * 2 + 1], aR, b + 2);
        }
    }

    // Epilogue: out = 1/(1+exp(v + B2)), float2 stores
    const int r0 = w * 16 + g;
    float bL0 = B2[r0],       bL1 = B2[r0 + 8];
    float bR0 = B2[128 + r0], bR1 = B2[128 + r0 + 8];

    #pragma unroll
    for (int nt = 0; nt < 8; nt++) {
        int t = t0 + nt * 8 + q * 2;
        float2 o;
        o.x = 1.0f / (1.0f + __expf(cL[nt][0] + bL0));
        o.y = 1.0f / (1.0f + __expf(cL[nt][1] + bL0));
        *(float2*)&out[(size_t)r0 * F + t] = o;
        o.x = 1.0f / (1.0f + __expf(cL[nt][2] + bL1));
        o.y = 1.0f / (1.0f + __expf(cL[nt][3] + bL1));
        *(float2*)&out[(size_t)(r0 + 8) * F + t] = o;
        o.x = 1.0f / (1.0f + __expf(cR[nt][0] + bR0));
        o.y = 1.0f / (1.0f + __expf(cR[nt][1] + bR0));
        *(float2*)&out[(size_t)(128 + r0) * F + t] = o;
        o.x = 1.0f / (1.0f + __expf(cR[nt][2] + bR1));
        o.y = 1.0f / (1.0f + __expf(cR[nt][3] + bR1));
        *(float2*)&out[(size_t)(128 + r0 + 8) * F + t] = o;
    }
}

// ---------------------------------------------------------------------------
extern "C" void kernel_launch(void* const* d_in, const int* in_sizes, int n_in,
                              void* d_out, int out_size)
{
    const float* X  = (const float*)d_in[0];
    const float* W1 = (const float*)d_in[1];
    const float* B1 = (const float*)d_in[2];
    const float* W2 = (const float*)d_in[3];
    const float* B2 = (const float*)d_in[4];
    float* out = (float*)d_out;

    cudaFuncSetAttribute(k1_gemm1, cudaFuncAttributeMaxDynamicSharedMemorySize, SMEM1);
    cudaFuncSetAttribute(k5_fused, cudaFuncAttributeMaxDynamicSharedMemorySize, SMEM5);

    k0_cvt<<<160, 256>>>(W1, W2);
    k1_gemm1<<<F / BN1, 512, SMEM1>>>(X, B1);
    k3a_prefix<<<NG, 128>>>();
    k3b_carry<<<1, 256>>>();
    k5_fused<<<NC / 2, 256, SMEM5>>>(B2, out);
}